// round 1
// baseline (speedup 1.0000x reference)
#include <cuda_runtime.h>
#include <math.h>

#define NHEADS 16
#define NKV 4
#define DH 64
#define NTOK 1024
#define DIM 1024
#define BS 32
#define NW 32
#define JW 33          // MEM + NW
#define NSEL 8
#define NBLK 9         // NSEL + own
#define JTOT 288       // NBLK*BS
#define CDIM 2048
#define HID 2048
#define QKVD 1536

// ---------------- scratch (static device globals; no runtime alloc) --------
__device__ float g_x[NTOK * DIM];
__device__ float g_qkv[NTOK * QKVD];
__device__ float g_pe[NKV * NW * CDIM];
__device__ float g_hid[NKV * NW * HID];
__device__ float g_craw[NKV * NW * DH];
__device__ float g_ck[NKV * JW * DH];
__device__ float g_cv[NKV * JW * DH];
__device__ float g_csim[NHEADS * NTOK * JW];
__device__ float g_cout[NHEADS * NTOK * DH];
__device__ float g_fout[NHEADS * NTOK * DH];
__device__ int   g_sel[NKV * NTOK * NBLK];
__device__ int   g_msk[NKV * NTOK * NBLK];
__device__ float g_gate[NTOK * 32];
__device__ float g_comb[NTOK * DIM];

// ---------------- RMSNorm ---------------------------------------------------
__global__ void rmsnorm_kernel(const float* __restrict__ inp,
                               const float* __restrict__ gw,
                               float* __restrict__ x) {
    int i = blockIdx.x, t = threadIdx.x;
    __shared__ float red[256];
    float s = 0.f;
    for (int d = t; d < DIM; d += 256) { float v = inp[i * DIM + d]; s += v * v; }
    red[t] = s; __syncthreads();
    for (int o = 128; o; o >>= 1) { if (t < o) red[t] += red[t + o]; __syncthreads(); }
    float r = 1.f / sqrtf(red[0] / (float)DIM + 1e-6f);
    for (int d = t; d < DIM; d += 256)
        x[i * DIM + d] = inp[i * DIM + d] * r * gw[d];
}

// ---------------- generic tiled fp32 GEMM: C = A(MxK) @ B(KxN) [+bias][relu]
template <bool RELU, bool HASBIAS>
__global__ void gemm_kernel(const float* __restrict__ A, const float* __restrict__ B,
                            const float* __restrict__ bias, float* __restrict__ C,
                            int M, int N, int K) {
    __shared__ float As[16][65];
    __shared__ float Bs[16][65];
    int bm = blockIdx.y * 64, bn = blockIdx.x * 64;
    int tid = threadIdx.x;                 // 256
    int tm = (tid >> 4) * 4, tn = (tid & 15) * 4;
    float acc[4][4] = {};
    for (int k0 = 0; k0 < K; k0 += 16) {
        for (int l = tid; l < 64 * 16; l += 256) {
            int m = l >> 4, kk = l & 15;
            As[kk][m] = (bm + m < M && k0 + kk < K) ? A[(bm + m) * K + k0 + kk] : 0.f;
        }
        for (int l = tid; l < 16 * 64; l += 256) {
            int kk = l >> 6, n = l & 63;
            Bs[kk][n] = (k0 + kk < K && bn + n < N) ? B[(k0 + kk) * N + bn + n] : 0.f;
        }
        __syncthreads();
#pragma unroll
        for (int kk = 0; kk < 16; kk++) {
            float a[4], b[4];
#pragma unroll
            for (int i = 0; i < 4; i++) a[i] = As[kk][tm + i];
#pragma unroll
            for (int j = 0; j < 4; j++) b[j] = Bs[kk][tn + j];
#pragma unroll
            for (int i = 0; i < 4; i++)
#pragma unroll
                for (int j = 0; j < 4; j++) acc[i][j] += a[i] * b[j];
        }
        __syncthreads();
    }
#pragma unroll
    for (int i = 0; i < 4; i++)
#pragma unroll
        for (int j = 0; j < 4; j++) {
            int m = bm + tm + i, n = bn + tn + j;
            if (m < M && n < N) {
                float v = acc[i][j];
                if (HASBIAS) v += bias[n];
                if (RELU) v = fmaxf(v, 0.f);
                C[m * N + n] = v;
            }
        }
}

// ---------------- build compress-MLP input rows (k or v + intra-block pos) --
__global__ void build_pe_kernel(const float* __restrict__ qkv,
                                const float* __restrict__ pos,
                                float* __restrict__ pe, int head_off) {
    int idx = blockIdx.x * 256 + threadIdx.x;   // NKV*NW*CDIM = 262144
    if (idx >= NKV * NW * CDIM) return;
    int d = idx & 63;
    int t = (idx >> 6) & 31;
    int w = (idx >> 11) & 31;
    int h = idx >> 16;
    pe[idx] = qkv[(w * BS + t) * QKVD + (head_off + h) * DH + d]
            + pos[(h * BS + t) * DH + d];
}

// ---------------- prepend mem token to compressed K/V -----------------------
__global__ void assemble_c_kernel(const float* __restrict__ raw,
                                  const float* __restrict__ mem_kv,
                                  float* __restrict__ c, int mem_off) {
    int idx = blockIdx.x * 256 + threadIdx.x;   // NKV*JW*DH = 8448
    if (idx >= NKV * JW * DH) return;
    int d = idx & 63;
    int j = (idx >> 6) % JW;
    int h = idx / (JW * DH);
    c[idx] = (j == 0) ? mem_kv[mem_off + h * DH + d]
                      : raw[(h * NW + (j - 1)) * DH + d];
}

// ---------------- compressed attention (pre-rotary q) -----------------------
__global__ void cattn_kernel(const float* __restrict__ qkv,
                             const float* __restrict__ ck,
                             const float* __restrict__ cv,
                             float* __restrict__ csim_out,
                             float* __restrict__ cout) {
    int i = blockIdx.x, head = blockIdx.y, kvh = head >> 2;
    int t = threadIdx.x;                 // 64
    __shared__ float qs[DH];
    __shared__ float sims[JW];
    __shared__ float probs[JW];
    qs[t] = qkv[i * QKVD + head * DH + t];
    __syncthreads();
    if (t < JW) {
        const float* kr = ck + (kvh * JW + t) * DH;
        float s = 0.f;
#pragma unroll
        for (int d = 0; d < DH; d++) s += qs[d] * kr[d];
        s *= 0.125f;                     // DH^-0.5
        sims[t] = s;
        csim_out[(head * NTOK + i) * JW + t] = s;
    }
    __syncthreads();
    if (t == 0) {
        float m = -1e30f;
        for (int j = 0; j < JW; j++) m = fmaxf(m, sims[j]);
        float den = 0.f;
        for (int j = 0; j < JW; j++) { float e = expf(sims[j] - m); probs[j] = e; den += e; }
        float inv = 1.f / den;
        for (int j = 0; j < JW; j++) probs[j] *= inv;
    }
    __syncthreads();
    float acc = 0.f;
    for (int j = 0; j < JW; j++) acc += probs[j] * cv[(kvh * JW + j) * DH + t];
    cout[(head * NTOK + i) * DH + t] = acc;
}

// ---------------- interleaved rotary on q + k (in-place in qkv) -------------
__global__ void rotary_kernel(float* __restrict__ qkv) {
    int i = blockIdx.x;
    int tid = threadIdx.x;               // 20 heads * 32 pairs = 640
    int hh = tid >> 5, p = tid & 31;
    float inv = powf(10000.f, -(float)(2 * p) / 64.f);
    float ang = (float)i * inv;
    float c = cosf(ang), s = sinf(ang);
    float* base = qkv + i * QKVD + hh * DH;
    float x0 = base[2 * p], x1 = base[2 * p + 1];
    base[2 * p]     = x0 * c - x1 * s;
    base[2 * p + 1] = x1 * c + x0 * s;
}

// ---------------- block selection (top-8 + own block) -----------------------
__global__ void select_kernel(const float* __restrict__ csim,
                              int* __restrict__ sel, int* __restrict__ msk) {
    int idx = blockIdx.x * blockDim.x + threadIdx.x;   // NKV*NTOK = 4096
    if (idx >= NKV * NTOK) return;
    int h = idx >> 10, i = idx & 1023;
    float imp[NW];
    for (int w = 0; w < NW; w++) {
        float s = 0.f;
        for (int g = 0; g < 4; g++)
            s += csim[((h * 4 + g) * NTOK + i) * JW + 1 + w];
        imp[w] = s * 0.25f;
    }
    float m = -1000.f;
    for (int w = 0; w < NW; w++) m = fmaxf(m, imp[w]);
    float den = expf(-1000.f - m);
    float p[NW];
    for (int w = 0; w < NW; w++) { p[w] = expf(imp[w] - m); den += p[w]; }
    float inv = 1.f / den;
    bool taken[NW];
    for (int w = 0; w < NW; w++) taken[w] = false;
    for (int s = 0; s < NSEL; s++) {
        int best = 0; float bv = -1.f;
        for (int w = 0; w < NW; w++)
            if (!taken[w] && p[w] > bv) { bv = p[w]; best = w; }
        taken[best] = true;
        sel[idx * NBLK + s] = best;
        msk[idx * NBLK + s] = (bv * inv > 1e-10f) ? 1 : 0;
    }
    sel[idx * NBLK + NSEL] = i >> 5;     // own block, always attended
    msk[idx * NBLK + NSEL] = 1;
}

// ---------------- fine (block-sparse) attention -----------------------------
__global__ void fattn_kernel(const float* __restrict__ qkv,
                             const int* __restrict__ sel,
                             const int* __restrict__ msk,
                             float* __restrict__ fout) {
    int i = blockIdx.x, kvh = blockIdx.y;
    int tid = threadIdx.x;               // 256
    __shared__ float qs[4][DH];
    __shared__ float kblk[BS][DH + 1];
    __shared__ float sims[4][JTOT];
    __shared__ int ssel[NBLK];
    __shared__ int smask[NBLK];
    __shared__ float gmax[4], ginv[4];
    if (tid < NBLK) {
        ssel[tid]  = sel[(kvh * NTOK + i) * NBLK + tid];
        smask[tid] = msk[(kvh * NTOK + i) * NBLK + tid];
    }
    { int g = tid >> 6, d = tid & 63;
      qs[g][d] = qkv[i * QKVD + (kvh * 4 + g) * DH + d]; }
    __syncthreads();
    for (int b = 0; b < NBLK; b++) {
        int blk = ssel[b];
        for (int l = tid; l < BS * DH; l += 256) {
            int t = l >> 6, d = l & 63;
            kblk[t][d] = qkv[(blk * BS + t) * QKVD + (16 + kvh) * DH + d];
        }
        __syncthreads();
        if (tid < 128) {
            int g = tid >> 5, t = tid & 31;
            float s = 0.f;
#pragma unroll
            for (int d = 0; d < DH; d++) s += qs[g][d] * kblk[t][d];
            sims[g][b * BS + t] = smask[b] ? s * 0.125f : -1e30f;
        }
        __syncthreads();
    }
    // softmax per g: warp w handles g=w
    int w = tid >> 5, lane = tid & 31;
    if (w < 4) {
        float m = -1e30f;
        for (int j = lane; j < JTOT; j += 32) m = fmaxf(m, sims[w][j]);
        for (int o = 16; o; o >>= 1) m = fmaxf(m, __shfl_xor_sync(0xffffffffu, m, o));
        float s = 0.f;
        for (int j = lane; j < JTOT; j += 32) s += expf(sims[w][j] - m);
        for (int o = 16; o; o >>= 1) s += __shfl_xor_sync(0xffffffffu, s, o);
        if (lane == 0) { gmax[w] = m; ginv[w] = 1.f / s; }
    }
    __syncthreads();
    for (int l = tid; l < 4 * JTOT; l += 256) {
        int g = l / JTOT, j = l % JTOT;
        sims[g][j] = expf(sims[g][j] - gmax[g]) * ginv[g];
    }
    __syncthreads();
    int g = tid >> 6, d = tid & 63;
    float acc = 0.f;
    for (int b = 0; b < NBLK; b++) {
        int blk = ssel[b];
        const float* vbase = qkv + (20 + kvh) * DH + d;
#pragma unroll
        for (int t = 0; t < BS; t++)
            acc += sims[g][b * BS + t] * vbase[(blk * BS + t) * QKVD];
    }
    fout[((kvh * 4 + g) * NTOK + i) * DH + d] = acc;
}

// ---------------- sigmoid-gated merge of the two branches -------------------
__global__ void combine_kernel(const float* __restrict__ gate_logits,
                               const float* __restrict__ cout,
                               const float* __restrict__ fout,
                               float* __restrict__ comb) {
    int idx = blockIdx.x * 256 + threadIdx.x;   // NTOK*DIM
    if (idx >= NTOK * DIM) return;
    int d = idx & 63, head = (idx >> 6) & 15, i = idx >> 10;
    float l0 = gate_logits[i * 32 + head * 2];
    float l1 = gate_logits[i * 32 + head * 2 + 1];
    float s0 = 1.f / (1.f + expf(-l0));
    float s1 = 1.f / (1.f + expf(-l1));
    comb[idx] = s0 * cout[(head * NTOK + i) * DH + d]
              + s1 * fout[(head * NTOK + i) * DH + d];
}

// ---------------- host launch -----------------------------------------------
extern "C" void kernel_launch(void* const* d_in, const int* in_sizes, int n_in,
                              void* d_out, int out_size) {
    const float* inp    = (const float*)d_in[0];
    const float* g_norm = (const float*)d_in[1];
    const float* w_qkv  = (const float*)d_in[2];
    const float* mem_kv = (const float*)d_in[3];
    const float* k_pos  = (const float*)d_in[4];
    const float* v_pos  = (const float*)d_in[5];
    const float* k_w1   = (const float*)d_in[6];
    const float* k_b1   = (const float*)d_in[7];
    const float* k_w2   = (const float*)d_in[8];
    const float* k_b2   = (const float*)d_in[9];
    const float* v_w1   = (const float*)d_in[10];
    const float* v_b1   = (const float*)d_in[11];
    const float* v_w2   = (const float*)d_in[12];
    const float* v_b2   = (const float*)d_in[13];
    const float* gate_w = (const float*)d_in[14];
    const float* gate_b = (const float*)d_in[15];
    const float* w_out  = (const float*)d_in[16];
    float* out = (float*)d_out;

    float *x, *qkv, *pe, *hid, *craw, *ck, *cv, *csim, *cout, *fout, *gate, *comb;
    int *sel, *msk;
    cudaGetSymbolAddress((void**)&x,    g_x);
    cudaGetSymbolAddress((void**)&qkv,  g_qkv);
    cudaGetSymbolAddress((void**)&pe,   g_pe);
    cudaGetSymbolAddress((void**)&hid,  g_hid);
    cudaGetSymbolAddress((void**)&craw, g_craw);
    cudaGetSymbolAddress((void**)&ck,   g_ck);
    cudaGetSymbolAddress((void**)&cv,   g_cv);
    cudaGetSymbolAddress((void**)&csim, g_csim);
    cudaGetSymbolAddress((void**)&cout, g_cout);
    cudaGetSymbolAddress((void**)&fout, g_fout);
    cudaGetSymbolAddress((void**)&gate, g_gate);
    cudaGetSymbolAddress((void**)&comb, g_comb);
    cudaGetSymbolAddress((void**)&sel,  g_sel);
    cudaGetSymbolAddress((void**)&msk,  g_msk);

    // 1. RMSNorm
    rmsnorm_kernel<<<NTOK, 256>>>(inp, g_norm, x);
    // 2. QKV projection (1024 x 1536 x 1024)
    gemm_kernel<false, false><<<dim3(QKVD / 64, NTOK / 64), 256>>>(
        x, w_qkv, nullptr, qkv, NTOK, QKVD, DIM);
    // 3. compressed-K MLP
    build_pe_kernel<<<(NKV * NW * CDIM + 255) / 256, 256>>>(qkv, k_pos, pe, 16);
    gemm_kernel<true, true><<<dim3(HID / 64, 2), 256>>>(
        pe, k_w1, k_b1, hid, NKV * NW, HID, CDIM);
    gemm_kernel<false, true><<<dim3(1, 2), 256>>>(
        hid, k_w2, k_b2, craw, NKV * NW, DH, HID);
    assemble_c_kernel<<<(NKV * JW * DH + 255) / 256, 256>>>(craw, mem_kv, ck, 0);
    // 4. compressed-V MLP
    build_pe_kernel<<<(NKV * NW * CDIM + 255) / 256, 256>>>(qkv, v_pos, pe, 20);
    gemm_kernel<true, true><<<dim3(HID / 64, 2), 256>>>(
        pe, v_w1, v_b1, hid, NKV * NW, HID, CDIM);
    gemm_kernel<false, true><<<dim3(1, 2), 256>>>(
        hid, v_w2, v_b2, craw, NKV * NW, DH, HID);
    assemble_c_kernel<<<(NKV * JW * DH + 255) / 256, 256>>>(craw, mem_kv, cv, NKV * DH);
    // 5. compressed attention (pre-rotary q)
    cattn_kernel<<<dim3(NTOK, NHEADS), 64>>>(qkv, ck, cv, csim, cout);
    // 6. rotary on q + k (in place)
    rotary_kernel<<<NTOK, 640>>>(qkv);
    // 7. block selection
    select_kernel<<<16, 256>>>(csim, sel, msk);
    // 8. fine block-sparse attention
    fattn_kernel<<<dim3(NTOK, NKV), 256>>>(qkv, sel, msk, fout);
    // 9. gates (1024 x 32 x 1024)
    gemm_kernel<false, true><<<dim3(1, NTOK / 64), 256>>>(
        x, gate_w, gate_b, gate, NTOK, 32, DIM);
    // 10. gated merge
    combine_kernel<<<(NTOK * DIM + 255) / 256, 256>>>(gate, cout, fout, comb);
    // 11. output projection (1024 x 1024 x 1024)
    gemm_kernel<false, false><<<dim3(DIM / 64, NTOK / 64), 256>>>(
        comb, w_out, nullptr, out, NTOK, DIM, DIM);
}

// round 2
// speedup vs baseline: 2.1984x; 2.1984x over previous
#include <cuda_runtime.h>
#include <math.h>

#define NHEADS 16
#define NKV 4
#define DH 64
#define NTOK 1024
#define DIM 1024
#define BS 32
#define NW 32
#define JW 33          // MEM + NW
#define NSEL 8
#define NBLK 9         // NSEL + own
#define JTOT 288       // NBLK*BS
#define CDIM 2048
#define HID 2048
#define QKVD 1536

// ---------------- scratch (static device globals; no runtime alloc) --------
__device__ float g_x[NTOK * DIM];
__device__ float g_qkv[NTOK * QKVD];
__device__ float g_pe[NKV * NW * CDIM];
__device__ float g_hid[NKV * NW * HID];
__device__ float g_craw[NKV * NW * DH];
__device__ float g_ck[NKV * JW * DH];
__device__ float g_cv[NKV * JW * DH];
__device__ float g_csim[NHEADS * NTOK * JW];
__device__ float g_cout[NHEADS * NTOK * DH];
__device__ float g_fout[NHEADS * NTOK * DH];
__device__ int   g_sel[NKV * NTOK * NBLK];
__device__ int   g_msk[NKV * NTOK * NBLK];
__device__ float g_gate[NTOK * 32];
__device__ float g_comb[NTOK * DIM];

// ---------------- RMSNorm ---------------------------------------------------
__global__ void rmsnorm_kernel(const float* __restrict__ inp,
                               const float* __restrict__ gw,
                               float* __restrict__ x) {
    int i = blockIdx.x, t = threadIdx.x;
    __shared__ float red[256];
    float s = 0.f;
    for (int d = t; d < DIM; d += 256) { float v = inp[i * DIM + d]; s += v * v; }
    red[t] = s; __syncthreads();
    for (int o = 128; o; o >>= 1) { if (t < o) red[t] += red[t + o]; __syncthreads(); }
    float r = 1.f / sqrtf(red[0] / (float)DIM + 1e-6f);
    for (int d = t; d < DIM; d += 256)
        x[i * DIM + d] = inp[i * DIM + d] * r * gw[d];
}

// ---------------- fast tiled fp32 GEMM: C = A(MxK) @ B(KxN) [+bias][relu] ---
// BM = TM*16, BN = 64, BK = 16, 256 threads, double-buffered smem,
// float4 global loads, float4/float2 smem reads. Requires:
//   M % BM == 0, N % 64 == 0, K % 16 == 0.
template <int TM, bool RELU, bool HASBIAS>
__global__ void gemm_kernel(const float* __restrict__ A, const float* __restrict__ B,
                            const float* __restrict__ bias, float* __restrict__ C,
                            int M, int N, int K) {
    constexpr int BM = TM * 16;
    __shared__ __align__(16) float As[2][16][BM + 4];
    __shared__ __align__(16) float Bs[2][16][68];
    int bm = blockIdx.y * BM, bn = blockIdx.x * 64;
    int tid = threadIdx.x;
    int ra = tid >> 2;            // A-load row (0..63)
    int ca = (tid & 3) * 4;       // A-load k offset
    int rb = tid >> 4;            // B-load k row (0..15)
    int cb = (tid & 15) * 4;      // B-load n offset
    int tm = (tid >> 4) * TM;
    int tn = (tid & 15) * 4;
    bool aActive = (ra < BM);
    float acc[TM][4] = {};
    int nk = K >> 4;
    float4 aReg = make_float4(0.f, 0.f, 0.f, 0.f), bReg;

    if (aActive) aReg = *(const float4*)&A[(bm + ra) * K + ca];
    bReg = *(const float4*)&B[rb * N + bn + cb];
    if (aActive) {
        As[0][ca + 0][ra] = aReg.x; As[0][ca + 1][ra] = aReg.y;
        As[0][ca + 2][ra] = aReg.z; As[0][ca + 3][ra] = aReg.w;
    }
    *(float4*)&Bs[0][rb][cb] = bReg;
    __syncthreads();

    int buf = 0;
    for (int kt = 0; kt < nk; kt++) {
        if (kt + 1 < nk) {
            int k0 = (kt + 1) << 4;
            if (aActive) aReg = *(const float4*)&A[(bm + ra) * K + k0 + ca];
            bReg = *(const float4*)&B[(k0 + rb) * N + bn + cb];
        }
#pragma unroll
        for (int kk = 0; kk < 16; kk++) {
            float a[TM], b[4];
            if (TM == 4) {
                float4 t4 = *(const float4*)&As[buf][kk][tm];
                a[0] = t4.x; a[1] = t4.y; a[2] = t4.z; a[3] = t4.w;
            } else {
                float2 t2 = *(const float2*)&As[buf][kk][tm];
                a[0] = t2.x; a[1] = t2.y;
            }
            float4 b4 = *(const float4*)&Bs[buf][kk][tn];
            b[0] = b4.x; b[1] = b4.y; b[2] = b4.z; b[3] = b4.w;
#pragma unroll
            for (int i = 0; i < TM; i++)
#pragma unroll
                for (int j = 0; j < 4; j++) acc[i][j] += a[i] * b[j];
        }
        if (kt + 1 < nk) {
            int nb = buf ^ 1;
            if (aActive) {
                As[nb][ca + 0][ra] = aReg.x; As[nb][ca + 1][ra] = aReg.y;
                As[nb][ca + 2][ra] = aReg.z; As[nb][ca + 3][ra] = aReg.w;
            }
            *(float4*)&Bs[nb][rb][cb] = bReg;
            __syncthreads();
            buf = nb;
        }
    }
#pragma unroll
    for (int i = 0; i < TM; i++) {
        float4 v;
        v.x = acc[i][0]; v.y = acc[i][1]; v.z = acc[i][2]; v.w = acc[i][3];
        if (HASBIAS) {
            v.x += bias[bn + tn + 0]; v.y += bias[bn + tn + 1];
            v.z += bias[bn + tn + 2]; v.w += bias[bn + tn + 3];
        }
        if (RELU) {
            v.x = fmaxf(v.x, 0.f); v.y = fmaxf(v.y, 0.f);
            v.z = fmaxf(v.z, 0.f); v.w = fmaxf(v.w, 0.f);
        }
        *(float4*)&C[(bm + tm + i) * N + bn + tn] = v;
    }
}

// ---------------- MLP layer 2: craw[128,64] = hid[128,2048] @ w2 + b2 -------
__global__ void mlp2_kernel(const float* __restrict__ hid,
                            const float* __restrict__ w2,
                            const float* __restrict__ b2,
                            float* __restrict__ craw) {
    int r = blockIdx.x;                  // 0..127
    int tid = threadIdx.x;               // 256
    int col = tid & 63, ks = tid >> 6;   // 4 k-slices of 512
    const float* hrow = hid + r * HID + ks * 512;
    const float* wb = w2 + ks * 512 * DH + col;
    float acc = 0.f;
#pragma unroll 8
    for (int k = 0; k < 512; k++) acc += hrow[k] * wb[k * DH];
    __shared__ float red[256];
    red[tid] = acc; __syncthreads();
    if (ks == 0)
        craw[r * DH + col] = red[col] + red[col + 64] + red[col + 128]
                           + red[col + 192] + b2[col];
}

// ---------------- gates: gate[1024,32] = x @ gate_w + gate_b ----------------
__global__ void gate_kernel(const float* __restrict__ x,
                            const float* __restrict__ gw,
                            const float* __restrict__ gb,
                            float* __restrict__ gate) {
    int i = blockIdx.x;                  // token
    int tid = threadIdx.x;               // 256
    int col = tid & 31, ks = tid >> 5;   // 8 k-slices of 128
    const float* xr = x + i * DIM + ks * 128;
    const float* wb = gw + ks * 128 * 32 + col;
    float acc = 0.f;
#pragma unroll 8
    for (int k = 0; k < 128; k++) acc += xr[k] * wb[k * 32];
    __shared__ float red[256];
    red[tid] = acc; __syncthreads();
    if (tid < 32) {
        float v = gb[col];
#pragma unroll
        for (int s = 0; s < 8; s++) v += red[col + s * 32];
        gate[i * 32 + col] = v;
    }
}

// ---------------- build compress-MLP input rows (k or v + intra-block pos) --
__global__ void build_pe_kernel(const float* __restrict__ qkv,
                                const float* __restrict__ pos,
                                float* __restrict__ pe, int head_off) {
    int idx = blockIdx.x * 256 + threadIdx.x;   // NKV*NW*CDIM = 262144
    if (idx >= NKV * NW * CDIM) return;
    int d = idx & 63;
    int t = (idx >> 6) & 31;
    int w = (idx >> 11) & 31;
    int h = idx >> 16;
    pe[idx] = qkv[(w * BS + t) * QKVD + (head_off + h) * DH + d]
            + pos[(h * BS + t) * DH + d];
}

// ---------------- prepend mem token to compressed K/V -----------------------
__global__ void assemble_c_kernel(const float* __restrict__ raw,
                                  const float* __restrict__ mem_kv,
                                  float* __restrict__ c, int mem_off) {
    int idx = blockIdx.x * 256 + threadIdx.x;   // NKV*JW*DH = 8448
    if (idx >= NKV * JW * DH) return;
    int d = idx & 63;
    int j = (idx >> 6) % JW;
    int h = idx / (JW * DH);
    c[idx] = (j == 0) ? mem_kv[mem_off + h * DH + d]
                      : raw[(h * NW + (j - 1)) * DH + d];
}

// ---------------- compressed attention (pre-rotary q) -----------------------
__global__ void cattn_kernel(const float* __restrict__ qkv,
                             const float* __restrict__ ck,
                             const float* __restrict__ cv,
                             float* __restrict__ csim_out,
                             float* __restrict__ cout) {
    int i = blockIdx.x, head = blockIdx.y, kvh = head >> 2;
    int t = threadIdx.x;                 // 64
    __shared__ float qs[DH];
    __shared__ float sims[JW];
    __shared__ float probs[JW];
    qs[t] = qkv[i * QKVD + head * DH + t];
    __syncthreads();
    if (t < JW) {
        const float* kr = ck + (kvh * JW + t) * DH;
        float s = 0.f;
#pragma unroll
        for (int d = 0; d < DH; d++) s += qs[d] * kr[d];
        s *= 0.125f;                     // DH^-0.5
        sims[t] = s;
        csim_out[(head * NTOK + i) * JW + t] = s;
    }
    __syncthreads();
    if (t == 0) {
        float m = -1e30f;
        for (int j = 0; j < JW; j++) m = fmaxf(m, sims[j]);
        float den = 0.f;
        for (int j = 0; j < JW; j++) { float e = expf(sims[j] - m); probs[j] = e; den += e; }
        float inv = 1.f / den;
        for (int j = 0; j < JW; j++) probs[j] *= inv;
    }
    __syncthreads();
    float acc = 0.f;
    for (int j = 0; j < JW; j++) acc += probs[j] * cv[(kvh * JW + j) * DH + t];
    cout[(head * NTOK + i) * DH + t] = acc;
}

// ---------------- interleaved rotary on q + k (in-place in qkv) -------------
__global__ void rotary_kernel(float* __restrict__ qkv) {
    int i = blockIdx.x;
    int tid = threadIdx.x;               // 20 heads * 32 pairs = 640
    int hh = tid >> 5, p = tid & 31;
    // 10000^(-2p/64) = exp2(-(2p/64)*log2(10000))
    float inv = exp2f(-(float)(2 * p) * (0.015625f * 13.287712379549449f));
    float ang = (float)i * inv;
    float c = cosf(ang), s = sinf(ang);
    float* base = qkv + i * QKVD + hh * DH;
    float x0 = base[2 * p], x1 = base[2 * p + 1];
    base[2 * p]     = x0 * c - x1 * s;
    base[2 * p + 1] = x1 * c + x0 * s;
}

// ---------------- block selection (top-8 + own block) -----------------------
__global__ void select_kernel(const float* __restrict__ csim,
                              int* __restrict__ sel, int* __restrict__ msk) {
    int idx = blockIdx.x * blockDim.x + threadIdx.x;   // NKV*NTOK = 4096
    if (idx >= NKV * NTOK) return;
    int h = idx >> 10, i = idx & 1023;
    float imp[NW];
    for (int w = 0; w < NW; w++) {
        float s = 0.f;
        for (int g = 0; g < 4; g++)
            s += csim[((h * 4 + g) * NTOK + i) * JW + 1 + w];
        imp[w] = s * 0.25f;
    }
    float m = -1000.f;
    for (int w = 0; w < NW; w++) m = fmaxf(m, imp[w]);
    float den = expf(-1000.f - m);
    float p[NW];
    for (int w = 0; w < NW; w++) { p[w] = expf(imp[w] - m); den += p[w]; }
    float inv = 1.f / den;
    bool taken[NW];
    for (int w = 0; w < NW; w++) taken[w] = false;
    for (int s = 0; s < NSEL; s++) {
        int best = 0; float bv = -1.f;
        for (int w = 0; w < NW; w++)
            if (!taken[w] && p[w] > bv) { bv = p[w]; best = w; }
        taken[best] = true;
        sel[idx * NBLK + s] = best;
        msk[idx * NBLK + s] = (bv * inv > 1e-10f) ? 1 : 0;
    }
    sel[idx * NBLK + NSEL] = i >> 5;     // own block, always attended
    msk[idx * NBLK + NSEL] = 1;
}

// ---------------- fine (block-sparse) attention -----------------------------
__global__ void fattn_kernel(const float* __restrict__ qkv,
                             const int* __restrict__ sel,
                             const int* __restrict__ msk,
                             float* __restrict__ fout) {
    int i = blockIdx.x, kvh = blockIdx.y;
    int tid = threadIdx.x;               // 256
    __shared__ float qs[4][DH];
    __shared__ float kblk[BS][DH + 1];
    __shared__ float sims[4][JTOT];
    __shared__ int ssel[NBLK];
    __shared__ int smask[NBLK];
    __shared__ float gmax[4], ginv[4];
    if (tid < NBLK) {
        ssel[tid]  = sel[(kvh * NTOK + i) * NBLK + tid];
        smask[tid] = msk[(kvh * NTOK + i) * NBLK + tid];
    }
    { int g = tid >> 6, d = tid & 63;
      qs[g][d] = qkv[i * QKVD + (kvh * 4 + g) * DH + d]; }
    __syncthreads();
    for (int b = 0; b < NBLK; b++) {
        int blk = ssel[b];
        for (int l = tid; l < BS * DH; l += 256) {
            int t = l >> 6, d = l & 63;
            kblk[t][d] = qkv[(blk * BS + t) * QKVD + (16 + kvh) * DH + d];
        }
        __syncthreads();
        if (tid < 128) {
            int g = tid >> 5, t = tid & 31;
            float s = 0.f;
#pragma unroll
            for (int d = 0; d < DH; d++) s += qs[g][d] * kblk[t][d];
            sims[g][b * BS + t] = smask[b] ? s * 0.125f : -1e30f;
        }
        __syncthreads();
    }
    int w = tid >> 5, lane = tid & 31;
    if (w < 4) {
        float m = -1e30f;
        for (int j = lane; j < JTOT; j += 32) m = fmaxf(m, sims[w][j]);
        for (int o = 16; o; o >>= 1) m = fmaxf(m, __shfl_xor_sync(0xffffffffu, m, o));
        float s = 0.f;
        for (int j = lane; j < JTOT; j += 32) s += expf(sims[w][j] - m);
        for (int o = 16; o; o >>= 1) s += __shfl_xor_sync(0xffffffffu, s, o);
        if (lane == 0) { gmax[w] = m; ginv[w] = 1.f / s; }
    }
    __syncthreads();
    for (int l = tid; l < 4 * JTOT; l += 256) {
        int g = l / JTOT, j = l % JTOT;
        sims[g][j] = expf(sims[g][j] - gmax[g]) * ginv[g];
    }
    __syncthreads();
    int g = tid >> 6, d = tid & 63;
    float acc = 0.f;
    for (int b = 0; b < NBLK; b++) {
        int blk = ssel[b];
        const float* vbase = qkv + (20 + kvh) * DH + d;
#pragma unroll
        for (int t = 0; t < BS; t++)
            acc += sims[g][b * BS + t] * vbase[(blk * BS + t) * QKVD];
    }
    fout[((kvh * 4 + g) * NTOK + i) * DH + d] = acc;
}

// ---------------- sigmoid-gated merge of the two branches -------------------
__global__ void combine_kernel(const float* __restrict__ gate_logits,
                               const float* __restrict__ cout,
                               const float* __restrict__ fout,
                               float* __restrict__ comb) {
    int idx = blockIdx.x * 256 + threadIdx.x;   // NTOK*DIM
    if (idx >= NTOK * DIM) return;
    int d = idx & 63, head = (idx >> 6) & 15, i = idx >> 10;
    float l0 = gate_logits[i * 32 + head * 2];
    float l1 = gate_logits[i * 32 + head * 2 + 1];
    float s0 = 1.f / (1.f + expf(-l0));
    float s1 = 1.f / (1.f + expf(-l1));
    comb[idx] = s0 * cout[(head * NTOK + i) * DH + d]
              + s1 * fout[(head * NTOK + i) * DH + d];
}

// ---------------- host launch -----------------------------------------------
extern "C" void kernel_launch(void* const* d_in, const int* in_sizes, int n_in,
                              void* d_out, int out_size) {
    const float* inp    = (const float*)d_in[0];
    const float* g_norm = (const float*)d_in[1];
    const float* w_qkv  = (const float*)d_in[2];
    const float* mem_kv = (const float*)d_in[3];
    const float* k_pos  = (const float*)d_in[4];
    const float* v_pos  = (const float*)d_in[5];
    const float* k_w1   = (const float*)d_in[6];
    const float* k_b1   = (const float*)d_in[7];
    const float* k_w2   = (const float*)d_in[8];
    const float* k_b2   = (const float*)d_in[9];
    const float* v_w1   = (const float*)d_in[10];
    const float* v_b1   = (const float*)d_in[11];
    const float* v_w2   = (const float*)d_in[12];
    const float* v_b2   = (const float*)d_in[13];
    const float* gate_w = (const float*)d_in[14];
    const float* gate_b = (const float*)d_in[15];
    const float* w_out  = (const float*)d_in[16];
    float* out = (float*)d_out;

    float *x, *qkv, *pe, *hid, *craw, *ck, *cv, *csim, *cout, *fout, *gate, *comb;
    int *sel, *msk;
    cudaGetSymbolAddress((void**)&x,    g_x);
    cudaGetSymbolAddress((void**)&qkv,  g_qkv);
    cudaGetSymbolAddress((void**)&pe,   g_pe);
    cudaGetSymbolAddress((void**)&hid,  g_hid);
    cudaGetSymbolAddress((void**)&craw, g_craw);
    cudaGetSymbolAddress((void**)&ck,   g_ck);
    cudaGetSymbolAddress((void**)&cv,   g_cv);
    cudaGetSymbolAddress((void**)&csim, g_csim);
    cudaGetSymbolAddress((void**)&cout, g_cout);
    cudaGetSymbolAddress((void**)&fout, g_fout);
    cudaGetSymbolAddress((void**)&gate, g_gate);
    cudaGetSymbolAddress((void**)&comb, g_comb);
    cudaGetSymbolAddress((void**)&sel,  g_sel);
    cudaGetSymbolAddress((void**)&msk,  g_msk);

    // 1. RMSNorm
    rmsnorm_kernel<<<NTOK, 256>>>(inp, g_norm, x);
    // 2. QKV projection (1024 x 1536 x 1024)
    gemm_kernel<4, false, false><<<dim3(QKVD / 64, NTOK / 64), 256>>>(
        x, w_qkv, nullptr, qkv, NTOK, QKVD, DIM);
    // 3. compressed-K MLP
    build_pe_kernel<<<(NKV * NW * CDIM + 255) / 256, 256>>>(qkv, k_pos, pe, 16);
    gemm_kernel<2, true, true><<<dim3(HID / 64, 4), 256>>>(
        pe, k_w1, k_b1, hid, NKV * NW, HID, CDIM);
    mlp2_kernel<<<NKV * NW, 256>>>(hid, k_w2, k_b2, craw);
    assemble_c_kernel<<<(NKV * JW * DH + 255) / 256, 256>>>(craw, mem_kv, ck, 0);
    // 4. compressed-V MLP
    build_pe_kernel<<<(NKV * NW * CDIM + 255) / 256, 256>>>(qkv, v_pos, pe, 20);
    gemm_kernel<2, true, true><<<dim3(HID / 64, 4), 256>>>(
        pe, v_w1, v_b1, hid, NKV * NW, HID, CDIM);
    mlp2_kernel<<<NKV * NW, 256>>>(hid, v_w2, v_b2, craw);
    assemble_c_kernel<<<(NKV * JW * DH + 255) / 256, 256>>>(craw, mem_kv, cv, NKV * DH);
    // 5. compressed attention (pre-rotary q)
    cattn_kernel<<<dim3(NTOK, NHEADS), 64>>>(qkv, ck, cv, csim, cout);
    // 6. rotary on q + k (in place)
    rotary_kernel<<<NTOK, 640>>>(qkv);
    // 7. block selection
    select_kernel<<<16, 256>>>(csim, sel, msk);
    // 8. fine block-sparse attention
    fattn_kernel<<<dim3(NTOK, NKV), 256>>>(qkv, sel, msk, fout);
    // 9. gates (1024 x 32 x 1024)
    gate_kernel<<<NTOK, 256>>>(x, gate_w, gate_b, gate);
    // 10. gated merge
    combine_kernel<<<(NTOK * DIM + 255) / 256, 256>>>(gate, cout, fout, comb);
    // 11. output projection (1024 x 1024 x 1024)
    gemm_kernel<4, false, false><<<dim3(DIM / 64, NTOK / 64), 256>>>(
        comb, w_out, nullptr, out, NTOK, DIM, DIM);
}

// round 3
// speedup vs baseline: 4.3605x; 1.9835x over previous
#include <cuda_runtime.h>
#include <math.h>

#define NHEADS 16
#define NKV 4
#define DH 64
#define NTOK 1024
#define DIM 1024
#define BS 32
#define NW 32
#define JW 33          // MEM + NW
#define NSEL 8
#define NBLK 9         // NSEL + own
#define JTOT 288       // NBLK*BS
#define CDIM 2048
#define HID 2048
#define QKVD 1536
#define PE_SZ (NKV * NW * CDIM)      // 262144 = 2^18
#define HID_SZ (NKV * NW * HID)      // 262144

// ---------------- scratch (static device globals; no runtime alloc) --------
__device__ float g_x[NTOK * DIM];
__device__ float g_qkv[NTOK * QKVD];
__device__ float g_pe[2 * PE_SZ];
__device__ float g_part[8 * HID_SZ];
__device__ float g_hid[2 * HID_SZ];
__device__ float g_craw[2 * NKV * NW * DH];
__device__ float g_ck[NKV * JW * DH];
__device__ float g_cv[NKV * JW * DH];
__device__ float g_csim[NHEADS * NTOK * JW];
__device__ float g_cout[NHEADS * NTOK * DH];
__device__ float g_fout[NHEADS * NTOK * DH];
__device__ int   g_sel[NKV * NTOK * NBLK];
__device__ int   g_msk[NKV * NTOK * NBLK];
__device__ float g_gate[NTOK * 32];
__device__ float g_comb[NTOK * DIM];

// ---------------- RMSNorm ---------------------------------------------------
__global__ void rmsnorm_kernel(const float* __restrict__ inp,
                               const float* __restrict__ gw,
                               float* __restrict__ x) {
    int i = blockIdx.x, t = threadIdx.x;
    __shared__ float red[256];
    float s = 0.f;
    for (int d = t; d < DIM; d += 256) { float v = inp[i * DIM + d]; s += v * v; }
    red[t] = s; __syncthreads();
    for (int o = 128; o; o >>= 1) { if (t < o) red[t] += red[t + o]; __syncthreads(); }
    float r = 1.f / sqrtf(red[0] / (float)DIM + 1e-6f);
    for (int d = t; d < DIM; d += 256)
        x[i * DIM + d] = inp[i * DIM + d] * r * gw[d];
}

// ---------------- shared GEMM tile body -------------------------------------
// C[bm:bm+BM, bn:bn+BN] = A(BMxK, lda) @ B(KxBN, ldb) [+bias][relu]
// NT = (BM/TM)*(BN/TN) threads, BK=16, double-buffered, float4 everywhere.
// Requires K%16==0, TN==4, lda/ldb/ldc %4==0.
template <int BM, int BN, int TM, int TN, bool RELU, bool HASBIAS>
__device__ __forceinline__ void gemm_body(
    const float* __restrict__ A, int lda,
    const float* __restrict__ B, int ldb,
    const float* __restrict__ bias,
    float* __restrict__ C, int ldc,
    int K, int bm, int bn)
{
    constexpr int NT = (BM / TM) * (BN / TN);
    constexpr int AVEC = BM * 4 / NT;   // float4 A-loads per thread
    constexpr int BVEC = BN * 4 / NT;   // float4 B-loads per thread
    __shared__ __align__(16) float As[2][16][BM + 4];
    __shared__ __align__(16) float Bs[2][16][BN + 4];
    int tid = threadIdx.x;
    int tx = tid % (BN / TN), ty = tid / (BN / TN);
    int tm = ty * TM, tn = tx * TN;

    float4 aR[AVEC], bR[BVEC];
#pragma unroll
    for (int v = 0; v < AVEC; v++) {
        int idx = v * NT + tid;
        aR[v] = *(const float4*)&A[(bm + (idx >> 2)) * lda + ((idx & 3) << 2)];
    }
#pragma unroll
    for (int v = 0; v < BVEC; v++) {
        int idx = v * NT + tid;
        bR[v] = *(const float4*)&B[(idx / (BN / 4)) * ldb + bn + ((idx % (BN / 4)) << 2)];
    }
#pragma unroll
    for (int v = 0; v < AVEC; v++) {
        int idx = v * NT + tid; int r = idx >> 2, c = (idx & 3) << 2;
        As[0][c + 0][r] = aR[v].x; As[0][c + 1][r] = aR[v].y;
        As[0][c + 2][r] = aR[v].z; As[0][c + 3][r] = aR[v].w;
    }
#pragma unroll
    for (int v = 0; v < BVEC; v++) {
        int idx = v * NT + tid;
        *(float4*)&Bs[0][idx / (BN / 4)][(idx % (BN / 4)) << 2] = bR[v];
    }
    __syncthreads();

    float acc[TM][TN] = {};
    int nk = K >> 4, buf = 0;
    for (int kt = 0; kt < nk; kt++) {
        if (kt + 1 < nk) {
            int k0 = (kt + 1) << 4;
#pragma unroll
            for (int v = 0; v < AVEC; v++) {
                int idx = v * NT + tid;
                aR[v] = *(const float4*)&A[(bm + (idx >> 2)) * lda + k0 + ((idx & 3) << 2)];
            }
#pragma unroll
            for (int v = 0; v < BVEC; v++) {
                int idx = v * NT + tid;
                bR[v] = *(const float4*)&B[(k0 + idx / (BN / 4)) * ldb + bn + ((idx % (BN / 4)) << 2)];
            }
        }
#pragma unroll
        for (int kk = 0; kk < 16; kk++) {
            float a[TM], b[TN];
#pragma unroll
            for (int i = 0; i < TM; i += 4) {
                float4 t4 = *(const float4*)&As[buf][kk][tm + i];
                a[i] = t4.x; a[i + 1] = t4.y; a[i + 2] = t4.z; a[i + 3] = t4.w;
            }
            float4 b4 = *(const float4*)&Bs[buf][kk][tn];
            b[0] = b4.x; b[1] = b4.y; b[2] = b4.z; b[3] = b4.w;
#pragma unroll
            for (int i = 0; i < TM; i++)
#pragma unroll
                for (int j = 0; j < TN; j++) acc[i][j] += a[i] * b[j];
        }
        if (kt + 1 < nk) {
            int nb = buf ^ 1;
#pragma unroll
            for (int v = 0; v < AVEC; v++) {
                int idx = v * NT + tid; int r = idx >> 2, c = (idx & 3) << 2;
                As[nb][c + 0][r] = aR[v].x; As[nb][c + 1][r] = aR[v].y;
                As[nb][c + 2][r] = aR[v].z; As[nb][c + 3][r] = aR[v].w;
            }
#pragma unroll
            for (int v = 0; v < BVEC; v++) {
                int idx = v * NT + tid;
                *(float4*)&Bs[nb][idx / (BN / 4)][(idx % (BN / 4)) << 2] = bR[v];
            }
            __syncthreads();
            buf = nb;
        }
    }
#pragma unroll
    for (int i = 0; i < TM; i++) {
        float4 v;
        v.x = acc[i][0]; v.y = acc[i][1]; v.z = acc[i][2]; v.w = acc[i][3];
        if (HASBIAS) {
            v.x += bias[bn + tn + 0]; v.y += bias[bn + tn + 1];
            v.z += bias[bn + tn + 2]; v.w += bias[bn + tn + 3];
        }
        if (RELU) {
            v.x = fmaxf(v.x, 0.f); v.y = fmaxf(v.y, 0.f);
            v.z = fmaxf(v.z, 0.f); v.w = fmaxf(v.w, 0.f);
        }
        *(float4*)&C[(bm + tm + i) * ldc + bn + tn] = v;
    }
}

// plain GEMM kernel (QKV, out-proj)
template <int BM, int BN, int TM, int TN>
__global__ void gemm2_kernel(const float* __restrict__ A, const float* __restrict__ B,
                             float* __restrict__ C, int N, int K) {
    gemm_body<BM, BN, TM, TN, false, false>(
        A, K, B, N, nullptr, C, N, K, blockIdx.y * BM, blockIdx.x * BN);
}

// fused K+V MLP layer-1 with split-K=4: partials into g_part
__global__ void mlp1_kernel(const float* __restrict__ pe,
                            const float* __restrict__ k_w1,
                            const float* __restrict__ v_w1,
                            float* __restrict__ part) {
    int z = blockIdx.z;              // kv*4 + kslice
    int kv = z >> 2, ks = z & 3;
    const float* A = pe + kv * PE_SZ + ks * 512;          // lda = CDIM
    const float* B = (kv ? v_w1 : k_w1) + ks * 512 * HID; // ldb = HID
    float* C = part + z * HID_SZ;                          // ldc = HID
    gemm_body<64, 64, 4, 4, false, false>(
        A, CDIM, B, HID, nullptr, C, HID, 512, blockIdx.y * 64, blockIdx.x * 64);
}

// reduce split-K partials + bias + relu -> hid
__global__ void mlp1_reduce_kernel(const float* __restrict__ part,
                                   const float* __restrict__ k_b1,
                                   const float* __restrict__ v_b1,
                                   float* __restrict__ hid) {
    int idx = blockIdx.x * 256 + threadIdx.x;   // 2*HID_SZ = 524288
    if (idx >= 2 * HID_SZ) return;
    int kv = idx >> 18;
    int rem = idx & (HID_SZ - 1);
    int n = rem & (HID - 1);
    float s = part[(kv * 4 + 0) * HID_SZ + rem] + part[(kv * 4 + 1) * HID_SZ + rem]
            + part[(kv * 4 + 2) * HID_SZ + rem] + part[(kv * 4 + 3) * HID_SZ + rem]
            + (kv ? v_b1[n] : k_b1[n]);
    hid[idx] = fmaxf(s, 0.f);
}

// fused K+V MLP layer 2: craw[kv][128,64] = hid[kv] @ w2 + b2
__global__ void mlp2_kernel(const float* __restrict__ hid,
                            const float* __restrict__ k_w2,
                            const float* __restrict__ v_w2,
                            const float* __restrict__ k_b2,
                            const float* __restrict__ v_b2,
                            float* __restrict__ craw) {
    int r = blockIdx.x, kv = blockIdx.y;
    int tid = threadIdx.x;               // 256
    int col = tid & 63, ks = tid >> 6;   // 4 k-slices of 512
    const float* hrow = hid + kv * HID_SZ + r * HID + ks * 512;
    const float* wb = (kv ? v_w2 : k_w2) + ks * 512 * DH + col;
    float acc = 0.f;
#pragma unroll 8
    for (int k = 0; k < 512; k++) acc += hrow[k] * wb[k * DH];
    __shared__ float red[256];
    red[tid] = acc; __syncthreads();
    if (ks == 0)
        craw[kv * (NKV * NW * DH) + r * DH + col] =
            red[col] + red[col + 64] + red[col + 128] + red[col + 192]
            + (kv ? v_b2[col] : k_b2[col]);
}

// ---------------- gates: gate[1024,32] = x @ gate_w + gate_b ----------------
__global__ void gate_kernel(const float* __restrict__ x,
                            const float* __restrict__ gw,
                            const float* __restrict__ gb,
                            float* __restrict__ gate) {
    int i = blockIdx.x;
    int tid = threadIdx.x;               // 256
    int col = tid & 31, ks = tid >> 5;
    const float* xr = x + i * DIM + ks * 128;
    const float* wb = gw + ks * 128 * 32 + col;
    float acc = 0.f;
#pragma unroll 8
    for (int k = 0; k < 128; k++) acc += xr[k] * wb[k * 32];
    __shared__ float red[256];
    red[tid] = acc; __syncthreads();
    if (tid < 32) {
        float v = gb[col];
#pragma unroll
        for (int s = 0; s < 8; s++) v += red[col + s * 32];
        gate[i * 32 + col] = v;
    }
}

// ---------------- fused build of both compress-MLP inputs -------------------
__global__ void build_pe_kernel(const float* __restrict__ qkv,
                                const float* __restrict__ k_pos,
                                const float* __restrict__ v_pos,
                                float* __restrict__ pe) {
    int idx = blockIdx.x * 256 + threadIdx.x;   // 2*PE_SZ
    if (idx >= 2 * PE_SZ) return;
    int kv = idx >> 18;
    int rem = idx & (PE_SZ - 1);
    int d = rem & 63;
    int t = (rem >> 6) & 31;
    int w = (rem >> 11) & 31;
    int h = rem >> 16;
    const float* pos = kv ? v_pos : k_pos;
    pe[idx] = qkv[(w * BS + t) * QKVD + ((kv ? 20 : 16) + h) * DH + d]
            + pos[(h * BS + t) * DH + d];
}

// ---------------- fused prepend of mem tokens to ck and cv ------------------
__global__ void assemble_c_kernel(const float* __restrict__ craw,
                                  const float* __restrict__ mem_kv,
                                  float* __restrict__ ck,
                                  float* __restrict__ cv) {
    int idx = blockIdx.x * 256 + threadIdx.x;   // 2*NKV*JW*DH = 16896
    if (idx >= 2 * NKV * JW * DH) return;
    int kv = idx / (NKV * JW * DH);
    int rem = idx % (NKV * JW * DH);
    int d = rem & 63;
    int j = (rem >> 6) % JW;
    int h = rem / (JW * DH);
    float* dst = kv ? cv : ck;
    dst[rem] = (j == 0) ? mem_kv[kv * (NKV * DH) + h * DH + d]
                        : craw[kv * (NKV * NW * DH) + (h * NW + (j - 1)) * DH + d];
}

// ---------------- compressed attention (pre-rotary q) -----------------------
__global__ void cattn_kernel(const float* __restrict__ qkv,
                             const float* __restrict__ ck,
                             const float* __restrict__ cv,
                             float* __restrict__ csim_out,
                             float* __restrict__ cout) {
    int i = blockIdx.x, head = blockIdx.y, kvh = head >> 2;
    int t = threadIdx.x;                 // 64
    __shared__ float qs[DH];
    __shared__ float sims[JW];
    __shared__ float probs[JW];
    __shared__ float sm_m, sm_inv;
    qs[t] = qkv[i * QKVD + head * DH + t];
    __syncthreads();
    if (t < JW) {
        const float* kr = ck + (kvh * JW + t) * DH;
        float s = 0.f;
#pragma unroll
        for (int d = 0; d < DH; d++) s += qs[d] * kr[d];
        s *= 0.125f;
        sims[t] = s;
        csim_out[(head * NTOK + i) * JW + t] = s;
    }
    __syncthreads();
    if (t < 32) {
        float m = sims[t];
        if (t == 0) m = fmaxf(m, sims[32]);
#pragma unroll
        for (int o = 16; o; o >>= 1) m = fmaxf(m, __shfl_xor_sync(0xffffffffu, m, o));
        float e = expf(sims[t] - m) + (t == 0 ? expf(sims[32] - m) : 0.f);
#pragma unroll
        for (int o = 16; o; o >>= 1) e += __shfl_xor_sync(0xffffffffu, e, o);
        if (t == 0) { sm_m = m; sm_inv = 1.f / e; }
    }
    __syncthreads();
    if (t < JW) probs[t] = expf(sims[t] - sm_m) * sm_inv;
    __syncthreads();
    float acc = 0.f;
    for (int j = 0; j < JW; j++) acc += probs[j] * cv[(kvh * JW + j) * DH + t];
    cout[(head * NTOK + i) * DH + t] = acc;
}

// ---------------- interleaved rotary on q + k (in-place in qkv) -------------
__global__ void rotary_kernel(float* __restrict__ qkv) {
    int i = blockIdx.x;
    int tid = threadIdx.x;               // 640
    int hh = tid >> 5, p = tid & 31;
    float inv = exp2f(-(float)(2 * p) * (0.015625f * 13.287712379549449f));
    float ang = (float)i * inv;
    float c = cosf(ang), s = sinf(ang);
    float* base = qkv + i * QKVD + hh * DH;
    float x0 = base[2 * p], x1 = base[2 * p + 1];
    base[2 * p]     = x0 * c - x1 * s;
    base[2 * p + 1] = x1 * c + x0 * s;
}

// ---------------- block selection (top-8 + own block) -----------------------
__global__ void select_kernel(const float* __restrict__ csim,
                              int* __restrict__ sel, int* __restrict__ msk) {
    int idx = blockIdx.x * blockDim.x + threadIdx.x;   // NKV*NTOK = 4096
    if (idx >= NKV * NTOK) return;
    int h = idx >> 10, i = idx & 1023;
    float imp[NW];
    for (int w = 0; w < NW; w++) {
        float s = 0.f;
        for (int g = 0; g < 4; g++)
            s += csim[((h * 4 + g) * NTOK + i) * JW + 1 + w];
        imp[w] = s * 0.25f;
    }
    float m = -1000.f;
    for (int w = 0; w < NW; w++) m = fmaxf(m, imp[w]);
    float den = expf(-1000.f - m);
    float p[NW];
    for (int w = 0; w < NW; w++) { p[w] = expf(imp[w] - m); den += p[w]; }
    float inv = 1.f / den;
    bool taken[NW];
    for (int w = 0; w < NW; w++) taken[w] = false;
    for (int s = 0; s < NSEL; s++) {
        int best = 0; float bv = -1.f;
        for (int w = 0; w < NW; w++)
            if (!taken[w] && p[w] > bv) { bv = p[w]; best = w; }
        taken[best] = true;
        sel[idx * NBLK + s] = best;
        msk[idx * NBLK + s] = (bv * inv > 1e-10f) ? 1 : 0;
    }
    sel[idx * NBLK + NSEL] = i >> 5;
    msk[idx * NBLK + NSEL] = 1;
}

// ---------------- fine (block-sparse) attention -----------------------------
__global__ void fattn_kernel(const float* __restrict__ qkv,
                             const int* __restrict__ sel,
                             const int* __restrict__ msk,
                             float* __restrict__ fout) {
    int i = blockIdx.x, kvh = blockIdx.y;
    int tid = threadIdx.x;               // 256
    __shared__ float qs[4][DH];
    __shared__ float kblk[BS][DH + 1];
    __shared__ float sims[4][JTOT];
    __shared__ int ssel[NBLK];
    __shared__ int smask[NBLK];
    __shared__ float gmax[4], ginv[4];
    if (tid < NBLK) {
        ssel[tid]  = sel[(kvh * NTOK + i) * NBLK + tid];
        smask[tid] = msk[(kvh * NTOK + i) * NBLK + tid];
    }
    { int g = tid >> 6, d = tid & 63;
      qs[g][d] = qkv[i * QKVD + (kvh * 4 + g) * DH + d]; }
    __syncthreads();
    for (int b = 0; b < NBLK; b++) {
        int blk = ssel[b];
        for (int l = tid; l < BS * DH; l += 256) {
            int t = l >> 6, d = l & 63;
            kblk[t][d] = qkv[(blk * BS + t) * QKVD + (16 + kvh) * DH + d];
        }
        __syncthreads();
        if (tid < 128) {
            int g = tid >> 5, t = tid & 31;
            float s = 0.f;
#pragma unroll
            for (int d = 0; d < DH; d++) s += qs[g][d] * kblk[t][d];
            sims[g][b * BS + t] = smask[b] ? s * 0.125f : -1e30f;
        }
        __syncthreads();
    }
    int w = tid >> 5, lane = tid & 31;
    if (w < 4) {
        float m = -1e30f;
        for (int j = lane; j < JTOT; j += 32) m = fmaxf(m, sims[w][j]);
        for (int o = 16; o; o >>= 1) m = fmaxf(m, __shfl_xor_sync(0xffffffffu, m, o));
        float s = 0.f;
        for (int j = lane; j < JTOT; j += 32) s += expf(sims[w][j] - m);
        for (int o = 16; o; o >>= 1) s += __shfl_xor_sync(0xffffffffu, s, o);
        if (lane == 0) { gmax[w] = m; ginv[w] = 1.f / s; }
    }
    __syncthreads();
    for (int l = tid; l < 4 * JTOT; l += 256) {
        int g = l / JTOT, j = l % JTOT;
        sims[g][j] = expf(sims[g][j] - gmax[g]) * ginv[g];
    }
    __syncthreads();
    int g = tid >> 6, d = tid & 63;
    float acc = 0.f;
    for (int b = 0; b < NBLK; b++) {
        int blk = ssel[b];
        const float* vbase = qkv + (20 + kvh) * DH + d;
#pragma unroll
        for (int t = 0; t < BS; t++)
            acc += sims[g][b * BS + t] * vbase[(blk * BS + t) * QKVD];
    }
    fout[((kvh * 4 + g) * NTOK + i) * DH + d] = acc;
}

// ---------------- sigmoid-gated merge of the two branches -------------------
__global__ void combine_kernel(const float* __restrict__ gate_logits,
                               const float* __restrict__ cout,
                               const float* __restrict__ fout,
                               float* __restrict__ comb) {
    int idx = blockIdx.x * 256 + threadIdx.x;
    if (idx >= NTOK * DIM) return;
    int d = idx & 63, head = (idx >> 6) & 15, i = idx >> 10;
    float l0 = gate_logits[i * 32 + head * 2];
    float l1 = gate_logits[i * 32 + head * 2 + 1];
    float s0 = 1.f / (1.f + expf(-l0));
    float s1 = 1.f / (1.f + expf(-l1));
    comb[idx] = s0 * cout[(head * NTOK + i) * DH + d]
              + s1 * fout[(head * NTOK + i) * DH + d];
}

// ---------------- host launch -----------------------------------------------
extern "C" void kernel_launch(void* const* d_in, const int* in_sizes, int n_in,
                              void* d_out, int out_size) {
    const float* inp    = (const float*)d_in[0];
    const float* g_norm = (const float*)d_in[1];
    const float* w_qkv  = (const float*)d_in[2];
    const float* mem_kv = (const float*)d_in[3];
    const float* k_pos  = (const float*)d_in[4];
    const float* v_pos  = (const float*)d_in[5];
    const float* k_w1   = (const float*)d_in[6];
    const float* k_b1   = (const float*)d_in[7];
    const float* k_w2   = (const float*)d_in[8];
    const float* k_b2   = (const float*)d_in[9];
    const float* v_w1   = (const float*)d_in[10];
    const float* v_b1   = (const float*)d_in[11];
    const float* v_w2   = (const float*)d_in[12];
    const float* v_b2   = (const float*)d_in[13];
    const float* gate_w = (const float*)d_in[14];
    const float* gate_b = (const float*)d_in[15];
    const float* w_out  = (const float*)d_in[16];
    float* out = (float*)d_out;

    float *x, *qkv, *pe, *part, *hid, *craw, *ck, *cv, *csim, *cout, *fout, *gate, *comb;
    int *sel, *msk;
    cudaGetSymbolAddress((void**)&x,    g_x);
    cudaGetSymbolAddress((void**)&qkv,  g_qkv);
    cudaGetSymbolAddress((void**)&pe,   g_pe);
    cudaGetSymbolAddress((void**)&part, g_part);
    cudaGetSymbolAddress((void**)&hid,  g_hid);
    cudaGetSymbolAddress((void**)&craw, g_craw);
    cudaGetSymbolAddress((void**)&ck,   g_ck);
    cudaGetSymbolAddress((void**)&cv,   g_cv);
    cudaGetSymbolAddress((void**)&csim, g_csim);
    cudaGetSymbolAddress((void**)&cout, g_cout);
    cudaGetSymbolAddress((void**)&fout, g_fout);
    cudaGetSymbolAddress((void**)&gate, g_gate);
    cudaGetSymbolAddress((void**)&comb, g_comb);
    cudaGetSymbolAddress((void**)&sel,  g_sel);
    cudaGetSymbolAddress((void**)&msk,  g_msk);

    // 1. RMSNorm
    rmsnorm_kernel<<<NTOK, 256>>>(inp, g_norm, x);
    // 2. QKV projection (1024 x 1536 x 1024)
    gemm2_kernel<128, 64, 8, 4><<<dim3(QKVD / 64, NTOK / 128), 256>>>(
        x, w_qkv, qkv, QKVD, DIM);
    // 3. fused K+V compress-MLP input
    build_pe_kernel<<<(2 * PE_SZ + 255) / 256, 256>>>(qkv, k_pos, v_pos, pe);
    // 4. fused K+V MLP layer 1 (split-K=4) + reduce
    mlp1_kernel<<<dim3(HID / 64, 2, 8), 256>>>(pe, k_w1, v_w1, part);
    mlp1_reduce_kernel<<<(2 * HID_SZ + 255) / 256, 256>>>(part, k_b1, v_b1, hid);
    // 5. fused K+V MLP layer 2
    mlp2_kernel<<<dim3(NKV * NW, 2), 256>>>(hid, k_w2, v_w2, k_b2, v_b2, craw);
    // 6. assemble ck / cv with mem token
    assemble_c_kernel<<<(2 * NKV * JW * DH + 255) / 256, 256>>>(craw, mem_kv, ck, cv);
    // 7. compressed attention (pre-rotary q)
    cattn_kernel<<<dim3(NTOK, NHEADS), 64>>>(qkv, ck, cv, csim, cout);
    // 8. rotary on q + k (in place)
    rotary_kernel<<<NTOK, 640>>>(qkv);
    // 9. block selection
    select_kernel<<<16, 256>>>(csim, sel, msk);
    // 10. fine block-sparse attention
    fattn_kernel<<<dim3(NTOK, NKV), 256>>>(qkv, sel, msk, fout);
    // 11. gates
    gate_kernel<<<NTOK, 256>>>(x, gate_w, gate_b, gate);
    // 12. gated merge
    combine_kernel<<<(NTOK * DIM + 255) / 256, 256>>>(gate, cout, fout, comb);
    // 13. output projection (1024 x 1024 x 1024)
    gemm2_kernel<128, 64, 8, 4><<<dim3(DIM / 64, NTOK / 128), 256>>>(
        comb, w_out, out, DIM, DIM);
}

// round 8
// speedup vs baseline: 5.0744x; 1.1637x over previous
#include <cuda_runtime.h>
#include <cuda_bf16.h>
#include <math.h>
#include <stdint.h>

#define NHEADS 16
#define NKV 4
#define DH 64
#define NTOK 1024
#define DIM 1024
#define BS 32
#define NW 32
#define JW 33          // MEM + NW
#define NSEL 8
#define NBLK 9         // NSEL + own
#define JTOT 288       // NBLK*BS
#define CDIM 2048
#define HID 2048
#define QKVD 1536
#define PE_SZ (NKV * NW * CDIM)      // 262144
#define HID_SZ (NKV * NW * HID)      // 262144

// ---------------- scratch (static device globals; no runtime alloc) --------
__device__ float g_x[NTOK * DIM];
__device__ float g_qkv[NTOK * QKVD];
__device__ float g_pe[2 * PE_SZ];
__device__ float g_part[8 * HID_SZ];
__device__ float g_hid[2 * HID_SZ];
__device__ float g_craw[2 * NKV * NW * DH];
__device__ float g_ck[NKV * JW * DH];
__device__ float g_cv[NKV * JW * DH];
__device__ float g_csim[NHEADS * NTOK * JW];
__device__ float g_cout[NHEADS * NTOK * DH];
__device__ float g_fout[NHEADS * NTOK * DH];
__device__ int   g_sel[NKV * NTOK * NBLK];
__device__ int   g_msk[NKV * NTOK * NBLK];
__device__ float g_gate[NTOK * 32];
__device__ float g_comb[NTOK * DIM];

// ============ HMMA (mma.sync m16n8k16 bf16) split-precision GEMM ============
// CTA: 256 threads = 8 warps in 4(m) x 2(n); CTA tile 128 x 64, k-chunk 32.
// smem row stride 40 bf16 (80B) -> conflict-free fragment loads.
// Layout per buffer (u32 units): Ahi[128*20] Alo[128*20] Bhi[64*20] Blo[64*20]
#define HS_ABUF 2560           // 128*20 u32
#define HS_BBUF 1280           // 64*20 u32
#define HS_BUF  (2 * HS_ABUF + 2 * HS_BBUF)   // 7680 u32
#define HS_BYTES (2 * HS_BUF * 4)             // 61440 bytes

__device__ __forceinline__ void mma16816(float* c, const uint32_t* a, const uint32_t* b) {
    asm volatile(
        "mma.sync.aligned.m16n8k16.row.col.f32.bf16.bf16.f32 "
        "{%0,%1,%2,%3}, {%4,%5,%6,%7}, {%8,%9}, {%0,%1,%2,%3};\n"
        : "+f"(c[0]), "+f"(c[1]), "+f"(c[2]), "+f"(c[3])
        : "r"(a[0]), "r"(a[1]), "r"(a[2]), "r"(a[3]), "r"(b[0]), "r"(b[1]));
}
__device__ __forceinline__ uint32_t pack_hi(float x, float y) {
    __nv_bfloat162 t(__float2bfloat16(x), __float2bfloat16(y));
    return *(uint32_t*)&t;
}
__device__ __forceinline__ uint32_t pack_lo(float x, float y) {
    __nv_bfloat16 hx = __float2bfloat16(x), hy = __float2bfloat16(y);
    __nv_bfloat162 t(__float2bfloat16(x - __bfloat162float(hx)),
                     __float2bfloat16(y - __bfloat162float(hy)));
    return *(uint32_t*)&t;
}

// C[bm:bm+128, bn:bn+64] = A(.,lda) @ B(.,ldb), fp32 out. K % 32 == 0.
__device__ __forceinline__ void hgemm_body(
    const float* __restrict__ A, int lda,
    const float* __restrict__ B, int ldb,
    float* __restrict__ C, int ldc,
    int K, int bm, int bn)
{
    extern __shared__ uint32_t smu[];
    int tid = threadIdx.x, wid = tid >> 5, lane = tid & 31;
    int mwarp = (wid & 3) * 32;          // warp m offset in CTA tile
    int nwarp = (wid >> 2) * 32;         // warp n offset
    int r = lane >> 2, cq = lane & 3;    // fragment row / k-pair index

    float4 aR[4], bR[2];
    float acc[2][4][4] = {};

    // prologue: load chunk 0
#pragma unroll
    for (int v = 0; v < 4; v++) {
        int idx = v * 256 + tid;
        aR[v] = *(const float4*)&A[(bm + (idx >> 3)) * lda + (idx & 7) * 4];
    }
#pragma unroll
    for (int v = 0; v < 2; v++) {
        int idx = v * 256 + tid;
        bR[v] = *(const float4*)&B[(idx >> 4) * ldb + bn + (idx & 15) * 4];
    }

    int nk = K >> 5;
    int buf = 0;
    // store chunk 0
    {
        uint32_t* Ahi = smu; uint32_t* Alo = smu + HS_ABUF;
        uint32_t* Bhi = smu + 2 * HS_ABUF; uint32_t* Blo = Bhi + HS_BBUF;
#pragma unroll
        for (int v = 0; v < 4; v++) {
            int idx = v * 256 + tid; int row = idx >> 3, q = idx & 7;
            uint2 h = make_uint2(pack_hi(aR[v].x, aR[v].y), pack_hi(aR[v].z, aR[v].w));
            uint2 l = make_uint2(pack_lo(aR[v].x, aR[v].y), pack_lo(aR[v].z, aR[v].w));
            *(uint2*)&Ahi[row * 20 + q * 2] = h;
            *(uint2*)&Alo[row * 20 + q * 2] = l;
        }
#pragma unroll
        for (int v = 0; v < 2; v++) {
            int idx = v * 256 + tid; int kr = idx >> 4, nq = (idx & 15) * 4;
            float bv[4] = {bR[v].x, bR[v].y, bR[v].z, bR[v].w};
#pragma unroll
            for (int j = 0; j < 4; j++) {
                __nv_bfloat16 h = __float2bfloat16(bv[j]);
                __nv_bfloat16 l = __float2bfloat16(bv[j] - __bfloat162float(h));
                ((__nv_bfloat16*)Bhi)[(nq + j) * 40 + kr] = h;
                ((__nv_bfloat16*)Blo)[(nq + j) * 40 + kr] = l;
            }
        }
    }
    __syncthreads();

    for (int kt = 0; kt < nk; kt++) {
        if (kt + 1 < nk) {
            int k0 = (kt + 1) << 5;
#pragma unroll
            for (int v = 0; v < 4; v++) {
                int idx = v * 256 + tid;
                aR[v] = *(const float4*)&A[(bm + (idx >> 3)) * lda + k0 + (idx & 7) * 4];
            }
#pragma unroll
            for (int v = 0; v < 2; v++) {
                int idx = v * 256 + tid;
                bR[v] = *(const float4*)&B[(k0 + (idx >> 4)) * ldb + bn + (idx & 15) * 4];
            }
        }
        uint32_t* Ahi = smu + buf * HS_BUF; uint32_t* Alo = Ahi + HS_ABUF;
        uint32_t* Bhi = Alo + HS_ABUF;      uint32_t* Blo = Bhi + HS_BBUF;
#pragma unroll
        for (int k16 = 0; k16 < 2; k16++) {
            int kp = k16 * 8;            // u32 pair offset for this k16
            uint32_t ah[2][4], al[2][4], bh[4][2], bl[4][2];
#pragma unroll
            for (int ma = 0; ma < 2; ma++) {
                int r0 = (mwarp + ma * 16 + r) * 20;
                ah[ma][0] = Ahi[r0 + kp + cq];        al[ma][0] = Alo[r0 + kp + cq];
                ah[ma][1] = Ahi[r0 + 160 + kp + cq];  al[ma][1] = Alo[r0 + 160 + kp + cq];
                ah[ma][2] = Ahi[r0 + kp + 4 + cq];    al[ma][2] = Alo[r0 + kp + 4 + cq];
                ah[ma][3] = Ahi[r0 + 160 + kp + 4 + cq]; al[ma][3] = Alo[r0 + 160 + kp + 4 + cq];
            }
#pragma unroll
            for (int na = 0; na < 4; na++) {
                int n0 = (nwarp + na * 8 + r) * 20;
                bh[na][0] = Bhi[n0 + kp + cq];     bl[na][0] = Blo[n0 + kp + cq];
                bh[na][1] = Bhi[n0 + kp + 4 + cq]; bl[na][1] = Blo[n0 + kp + 4 + cq];
            }
#pragma unroll
            for (int ma = 0; ma < 2; ma++)
#pragma unroll
                for (int na = 0; na < 4; na++) {
                    mma16816(acc[ma][na], ah[ma], bh[na]);
                    mma16816(acc[ma][na], ah[ma], bl[na]);
                    mma16816(acc[ma][na], al[ma], bh[na]);
                }
        }
        if (kt + 1 < nk) {
            uint32_t* nAhi = smu + (buf ^ 1) * HS_BUF; uint32_t* nAlo = nAhi + HS_ABUF;
            uint32_t* nBhi = nAlo + HS_ABUF;           uint32_t* nBlo = nBhi + HS_BBUF;
#pragma unroll
            for (int v = 0; v < 4; v++) {
                int idx = v * 256 + tid; int row = idx >> 3, q = idx & 7;
                uint2 h = make_uint2(pack_hi(aR[v].x, aR[v].y), pack_hi(aR[v].z, aR[v].w));
                uint2 l = make_uint2(pack_lo(aR[v].x, aR[v].y), pack_lo(aR[v].z, aR[v].w));
                *(uint2*)&nAhi[row * 20 + q * 2] = h;
                *(uint2*)&nAlo[row * 20 + q * 2] = l;
            }
#pragma unroll
            for (int v = 0; v < 2; v++) {
                int idx = v * 256 + tid; int kr = idx >> 4, nq = (idx & 15) * 4;
                float bv[4] = {bR[v].x, bR[v].y, bR[v].z, bR[v].w};
#pragma unroll
                for (int j = 0; j < 4; j++) {
                    __nv_bfloat16 h = __float2bfloat16(bv[j]);
                    __nv_bfloat16 l = __float2bfloat16(bv[j] - __bfloat162float(h));
                    ((__nv_bfloat16*)nBhi)[(nq + j) * 40 + kr] = h;
                    ((__nv_bfloat16*)nBlo)[(nq + j) * 40 + kr] = l;
                }
            }
            __syncthreads();
            buf ^= 1;
        }
    }
    // epilogue
#pragma unroll
    for (int ma = 0; ma < 2; ma++)
#pragma unroll
        for (int na = 0; na < 4; na++) {
            int row = bm + mwarp + ma * 16 + r;
            int col = bn + nwarp + na * 8 + cq * 2;
            *(float2*)&C[row * ldc + col] =
                make_float2(acc[ma][na][0], acc[ma][na][1]);
            *(float2*)&C[(row + 8) * ldc + col] =
                make_float2(acc[ma][na][2], acc[ma][na][3]);
        }
}

__global__ void hgemm_kernel(const float* __restrict__ A, int lda,
                             const float* __restrict__ B, int ldb,
                             float* __restrict__ C, int ldc, int K) {
    hgemm_body(A, lda, B, ldb, C, ldc, K, blockIdx.y * 128, blockIdx.x * 64);
}

__global__ void mlp1_h_kernel(const float* __restrict__ pe,
                              const float* __restrict__ k_w1,
                              const float* __restrict__ v_w1,
                              float* __restrict__ part) {
    int z = blockIdx.z;                  // kv*4 + ks
    int kv = z >> 2, ks = z & 3;
    hgemm_body(pe + kv * PE_SZ + ks * 512, CDIM,
               (kv ? v_w1 : k_w1) + ks * 512 * HID, HID,
               part + z * HID_SZ, HID, 512, 0, blockIdx.x * 64);
}

// ---------------- RMSNorm ---------------------------------------------------
__global__ void rmsnorm_kernel(const float* __restrict__ inp,
                               const float* __restrict__ gw,
                               float* __restrict__ x) {
    int i = blockIdx.x, t = threadIdx.x;
    __shared__ float red[256];
    float s = 0.f;
    for (int d = t; d < DIM; d += 256) { float v = inp[i * DIM + d]; s += v * v; }
    red[t] = s; __syncthreads();
    for (int o = 128; o; o >>= 1) { if (t < o) red[t] += red[t + o]; __syncthreads(); }
    float r = 1.f / sqrtf(red[0] / (float)DIM + 1e-6f);
    for (int d = t; d < DIM; d += 256)
        x[i * DIM + d] = inp[i * DIM + d] * r * gw[d];
}

// reduce split-K partials + bias + relu -> hid
__global__ void mlp1_reduce_kernel(const float* __restrict__ part,
                                   const float* __restrict__ k_b1,
                                   const float* __restrict__ v_b1,
                                   float* __restrict__ hid) {
    int idx = blockIdx.x * 256 + threadIdx.x;   // 2*HID_SZ
    if (idx >= 2 * HID_SZ) return;
    int kv = idx >> 18;
    int rem = idx & (HID_SZ - 1);
    int n = rem & (HID - 1);
    float s = part[(kv * 4 + 0) * HID_SZ + rem] + part[(kv * 4 + 1) * HID_SZ + rem]
            + part[(kv * 4 + 2) * HID_SZ + rem] + part[(kv * 4 + 3) * HID_SZ + rem]
            + (kv ? v_b1[n] : k_b1[n]);
    hid[idx] = fmaxf(s, 0.f);
}

// fused K+V MLP layer 2
__global__ void mlp2_kernel(const float* __restrict__ hid,
                            const float* __restrict__ k_w2,
                            const float* __restrict__ v_w2,
                            const float* __restrict__ k_b2,
                            const float* __restrict__ v_b2,
                            float* __restrict__ craw) {
    int r = blockIdx.x, kv = blockIdx.y;
    int tid = threadIdx.x;               // 256
    int col = tid & 63, ks = tid >> 6;
    const float* hrow = hid + kv * HID_SZ + r * HID + ks * 512;
    const float* wb = (kv ? v_w2 : k_w2) + ks * 512 * DH + col;
    float acc = 0.f;
#pragma unroll 8
    for (int k = 0; k < 512; k++) acc += hrow[k] * wb[k * DH];
    __shared__ float red[256];
    red[tid] = acc; __syncthreads();
    if (ks == 0)
        craw[kv * (NKV * NW * DH) + r * DH + col] =
            red[col] + red[col + 64] + red[col + 128] + red[col + 192]
            + (kv ? v_b2[col] : k_b2[col]);
}

// ---------------- gates -----------------------------------------------------
__global__ void gate_kernel(const float* __restrict__ x,
                            const float* __restrict__ gw,
                            const float* __restrict__ gb,
                            float* __restrict__ gate) {
    int i = blockIdx.x;
    int tid = threadIdx.x;               // 256
    int col = tid & 31, ks = tid >> 5;
    const float* xr = x + i * DIM + ks * 128;
    const float* wb = gw + ks * 128 * 32 + col;
    float acc = 0.f;
#pragma unroll 8
    for (int k = 0; k < 128; k++) acc += xr[k] * wb[k * 32];
    __shared__ float red[256];
    red[tid] = acc; __syncthreads();
    if (tid < 32) {
        float v = gb[col];
#pragma unroll
        for (int s = 0; s < 8; s++) v += red[col + s * 32];
        gate[i * 32 + col] = v;
    }
}

// ---------------- fused build of both compress-MLP inputs -------------------
__global__ void build_pe_kernel(const float* __restrict__ qkv,
                                const float* __restrict__ k_pos,
                                const float* __restrict__ v_pos,
                                float* __restrict__ pe) {
    int idx = blockIdx.x * 256 + threadIdx.x;   // 2*PE_SZ
    if (idx >= 2 * PE_SZ) return;
    int kv = idx >> 18;
    int rem = idx & (PE_SZ - 1);
    int d = rem & 63;
    int t = (rem >> 6) & 31;
    int w = (rem >> 11) & 31;
    int h = rem >> 16;
    const float* pos = kv ? v_pos : k_pos;
    pe[idx] = qkv[(w * BS + t) * QKVD + ((kv ? 20 : 16) + h) * DH + d]
            + pos[(h * BS + t) * DH + d];
}

// ---------------- fused prepend of mem tokens to ck and cv ------------------
__global__ void assemble_c_kernel(const float* __restrict__ craw,
                                  const float* __restrict__ mem_kv,
                                  float* __restrict__ ck,
                                  float* __restrict__ cv) {
    int idx = blockIdx.x * 256 + threadIdx.x;
    if (idx >= 2 * NKV * JW * DH) return;
    int kv = idx / (NKV * JW * DH);
    int rem = idx % (NKV * JW * DH);
    int d = rem & 63;
    int j = (rem >> 6) % JW;
    int h = rem / (JW * DH);
    float* dst = kv ? cv : ck;
    dst[rem] = (j == 0) ? mem_kv[kv * (NKV * DH) + h * DH + d]
                        : craw[kv * (NKV * NW * DH) + (h * NW + (j - 1)) * DH + d];
}

// ---------------- compressed attention (pre-rotary q) -----------------------
__global__ void cattn_kernel(const float* __restrict__ qkv,
                             const float* __restrict__ ck,
                             const float* __restrict__ cv,
                             float* __restrict__ csim_out,
                             float* __restrict__ cout) {
    int i = blockIdx.x, head = blockIdx.y, kvh = head >> 2;
    int t = threadIdx.x;                 // 64
    __shared__ float qs[DH];
    __shared__ float sims[JW];
    __shared__ float probs[JW];
    __shared__ float sm_m, sm_inv;
    qs[t] = qkv[i * QKVD + head * DH + t];
    __syncthreads();
    if (t < JW) {
        const float* kr = ck + (kvh * JW + t) * DH;
        float s = 0.f;
#pragma unroll
        for (int d = 0; d < DH; d++) s += qs[d] * kr[d];
        s *= 0.125f;
        sims[t] = s;
        csim_out[(head * NTOK + i) * JW + t] = s;
    }
    __syncthreads();
    if (t < 32) {
        float m = sims[t];
        if (t == 0) m = fmaxf(m, sims[32]);
#pragma unroll
        for (int o = 16; o; o >>= 1) m = fmaxf(m, __shfl_xor_sync(0xffffffffu, m, o));
        float e = expf(sims[t] - m) + (t == 0 ? expf(sims[32] - m) : 0.f);
#pragma unroll
        for (int o = 16; o; o >>= 1) e += __shfl_xor_sync(0xffffffffu, e, o);
        if (t == 0) { sm_m = m; sm_inv = 1.f / e; }
    }
    __syncthreads();
    if (t < JW) probs[t] = expf(sims[t] - sm_m) * sm_inv;
    __syncthreads();
    float acc = 0.f;
    for (int j = 0; j < JW; j++) acc += probs[j] * cv[(kvh * JW + j) * DH + t];
    cout[(head * NTOK + i) * DH + t] = acc;
}

// ---------------- interleaved rotary on q + k (in-place in qkv) -------------
__global__ void rotary_kernel(float* __restrict__ qkv) {
    int i = blockIdx.x;
    int tid = threadIdx.x;               // 640
    int hh = tid >> 5, p = tid & 31;
    float inv = exp2f(-(float)(2 * p) * (0.015625f * 13.287712379549449f));
    float ang = (float)i * inv;
    float c = cosf(ang), s = sinf(ang);
    float* base = qkv + i * QKVD + hh * DH;
    float x0 = base[2 * p], x1 = base[2 * p + 1];
    base[2 * p]     = x0 * c - x1 * s;
    base[2 * p + 1] = x1 * c + x0 * s;
}

// ---------------- block selection (top-8 + own block) -----------------------
__global__ void select_kernel(const float* __restrict__ csim,
                              int* __restrict__ sel, int* __restrict__ msk) {
    int idx = blockIdx.x * blockDim.x + threadIdx.x;   // NKV*NTOK = 4096
    if (idx >= NKV * NTOK) return;
    int h = idx >> 10, i = idx & 1023;
    float imp[NW];
    for (int w = 0; w < NW; w++) {
        float s = 0.f;
        for (int g = 0; g < 4; g++)
            s += csim[((h * 4 + g) * NTOK + i) * JW + 1 + w];
        imp[w] = s * 0.25f;
    }
    float m = -1000.f;
    for (int w = 0; w < NW; w++) m = fmaxf(m, imp[w]);
    float den = expf(-1000.f - m);
    float p[NW];
    for (int w = 0; w < NW; w++) { p[w] = expf(imp[w] - m); den += p[w]; }
    float inv = 1.f / den;
    bool taken[NW];
    for (int w = 0; w < NW; w++) taken[w] = false;
    for (int s = 0; s < NSEL; s++) {
        int best = 0; float bv = -1.f;
        for (int w = 0; w < NW; w++)
            if (!taken[w] && p[w] > bv) { bv = p[w]; best = w; }
        taken[best] = true;
        sel[idx * NBLK + s] = best;
        msk[idx * NBLK + s] = (bv * inv > 1e-10f) ? 1 : 0;
    }
    sel[idx * NBLK + NSEL] = i >> 5;
    msk[idx * NBLK + NSEL] = 1;
}

// ---------------- fine (block-sparse) attention -----------------------------
__global__ void fattn_kernel(const float* __restrict__ qkv,
                             const int* __restrict__ sel,
                             const int* __restrict__ msk,
                             float* __restrict__ fout) {
    int i = blockIdx.x, kvh = blockIdx.y;
    int tid = threadIdx.x;               // 256
    __shared__ float qs[4][DH];
    __shared__ float kblk[BS][DH + 1];
    __shared__ float sims[4][JTOT];
    __shared__ int ssel[NBLK];
    __shared__ int smask[NBLK];
    __shared__ float gmax[4], ginv[4];
    if (tid < NBLK) {
        ssel[tid]  = sel[(kvh * NTOK + i) * NBLK + tid];
        smask[tid] = msk[(kvh * NTOK + i) * NBLK + tid];
    }
    { int g = tid >> 6, d = tid & 63;
      qs[g][d] = qkv[i * QKVD + (kvh * 4 + g) * DH + d]; }
    __syncthreads();
    for (int b = 0; b < NBLK; b++) {
        int blk = ssel[b];
        for (int l = tid; l < BS * DH; l += 256) {
            int t = l >> 6, d = l & 63;
            kblk[t][d] = qkv[(blk * BS + t) * QKVD + (16 + kvh) * DH + d];
        }
        __syncthreads();
        if (tid < 128) {
            int g = tid >> 5, t = tid & 31;
            float s = 0.f;
#pragma unroll
            for (int d = 0; d < DH; d++) s += qs[g][d] * kblk[t][d];
            sims[g][b * BS + t] = smask[b] ? s * 0.125f : -1e30f;
        }
        __syncthreads();
    }
    int w = tid >> 5, lane = tid & 31;
    if (w < 4) {
        float m = -1e30f;
        for (int j = lane; j < JTOT; j += 32) m = fmaxf(m, sims[w][j]);
        for (int o = 16; o; o >>= 1) m = fmaxf(m, __shfl_xor_sync(0xffffffffu, m, o));
        float s = 0.f;
        for (int j = lane; j < JTOT; j += 32) s += expf(sims[w][j] - m);
        for (int o = 16; o; o >>= 1) s += __shfl_xor_sync(0xffffffffu, s, o);
        if (lane == 0) { gmax[w] = m; ginv[w] = 1.f / s; }
    }
    __syncthreads();
    for (int l = tid; l < 4 * JTOT; l += 256) {
        int g = l / JTOT, j = l % JTOT;
        sims[g][j] = expf(sims[g][j] - gmax[g]) * ginv[g];
    }
    __syncthreads();
    int g = tid >> 6, d = tid & 63;
    float acc = 0.f;
    for (int b = 0; b < NBLK; b++) {
        int blk = ssel[b];
        const float* vbase = qkv + (20 + kvh) * DH + d;
#pragma unroll
        for (int t = 0; t < BS; t++)
            acc += sims[g][b * BS + t] * vbase[(blk * BS + t) * QKVD];
    }
    fout[((kvh * 4 + g) * NTOK + i) * DH + d] = acc;
}

// ---------------- sigmoid-gated merge of the two branches -------------------
__global__ void combine_kernel(const float* __restrict__ gate_logits,
                               const float* __restrict__ cout,
                               const float* __restrict__ fout,
                               float* __restrict__ comb) {
    int idx = blockIdx.x * 256 + threadIdx.x;
    if (idx >= NTOK * DIM) return;
    int d = idx & 63, head = (idx >> 6) & 15, i = idx >> 10;
    float l0 = gate_logits[i * 32 + head * 2];
    float l1 = gate_logits[i * 32 + head * 2 + 1];
    float s0 = 1.f / (1.f + expf(-l0));
    float s1 = 1.f / (1.f + expf(-l1));
    comb[idx] = s0 * cout[(head * NTOK + i) * DH + d]
              + s1 * fout[(head * NTOK + i) * DH + d];
}

// ---------------- host launch -----------------------------------------------
extern "C" void kernel_launch(void* const* d_in, const int* in_sizes, int n_in,
                              void* d_out, int out_size) {
    const float* inp    = (const float*)d_in[0];
    const float* g_norm = (const float*)d_in[1];
    const float* w_qkv  = (const float*)d_in[2];
    const float* mem_kv = (const float*)d_in[3];
    const float* k_pos  = (const float*)d_in[4];
    const float* v_pos  = (const float*)d_in[5];
    const float* k_w1   = (const float*)d_in[6];
    const float* k_b1   = (const float*)d_in[7];
    const float* k_w2   = (const float*)d_in[8];
    const float* k_b2   = (const float*)d_in[9];
    const float* v_w1   = (const float*)d_in[10];
    const float* v_b1   = (const float*)d_in[11];
    const float* v_w2   = (const float*)d_in[12];
    const float* v_b2   = (const float*)d_in[13];
    const float* gate_w = (const float*)d_in[14];
    const float* gate_b = (const float*)d_in[15];
    const float* w_out  = (const float*)d_in[16];
    float* out = (float*)d_out;

    float *x, *qkv, *pe, *part, *hid, *craw, *ck, *cv, *csim, *cout, *fout, *gate, *comb;
    int *sel, *msk;
    cudaGetSymbolAddress((void**)&x,    g_x);
    cudaGetSymbolAddress((void**)&qkv,  g_qkv);
    cudaGetSymbolAddress((void**)&pe,   g_pe);
    cudaGetSymbolAddress((void**)&part, g_part);
    cudaGetSymbolAddress((void**)&hid,  g_hid);
    cudaGetSymbolAddress((void**)&craw, g_craw);
    cudaGetSymbolAddress((void**)&ck,   g_ck);
    cudaGetSymbolAddress((void**)&cv,   g_cv);
    cudaGetSymbolAddress((void**)&csim, g_csim);
    cudaGetSymbolAddress((void**)&cout, g_cout);
    cudaGetSymbolAddress((void**)&fout, g_fout);
    cudaGetSymbolAddress((void**)&gate, g_gate);
    cudaGetSymbolAddress((void**)&comb, g_comb);
    cudaGetSymbolAddress((void**)&sel,  g_sel);
    cudaGetSymbolAddress((void**)&msk,  g_msk);

    cudaFuncSetAttribute(hgemm_kernel,
        cudaFuncAttributeMaxDynamicSharedMemorySize, HS_BYTES);
    cudaFuncSetAttribute(mlp1_h_kernel,
        cudaFuncAttributeMaxDynamicSharedMemorySize, HS_BYTES);

    // 1. RMSNorm
    rmsnorm_kernel<<<NTOK, 256>>>(inp, g_norm, x);
    // 2. QKV projection (HMMA): 1024 x 1536 x 1024
    hgemm_kernel<<<dim3(QKVD / 64, NTOK / 128), 256, HS_BYTES>>>(
        x, DIM, w_qkv, QKVD, qkv, QKVD, DIM);
    // 3. fused K+V compress-MLP input
    build_pe_kernel<<<(2 * PE_SZ + 255) / 256, 256>>>(qkv, k_pos, v_pos, pe);
    // 4. fused K+V MLP layer 1 (HMMA, split-K=4) + reduce
    mlp1_h_kernel<<<dim3(HID / 64, 1, 8), 256, HS_BYTES>>>(pe, k_w1, v_w1, part);
    mlp1_reduce_kernel<<<(2 * HID_SZ + 255) / 256, 256>>>(part, k_b1, v_b1, hid);
    // 5. fused K+V MLP layer 2
    mlp2_kernel<<<dim3(NKV * NW, 2), 256>>>(hid, k_w2, v_w2, k_b2, v_b2, craw);
    // 6. assemble ck / cv with mem token
    assemble_c_kernel<<<(2 * NKV * JW * DH + 255) / 256, 256>>>(craw, mem_kv, ck, cv);
    // 7. compressed attention (pre-rotary q)
    cattn_kernel<<<dim3(NTOK, NHEADS), 64>>>(qkv, ck, cv, csim, cout);
    // 8. rotary on q + k (in place)
    rotary_kernel<<<NTOK, 640>>>(qkv);
    // 9. block selection
    select_kernel<<<16, 256>>>(csim, sel, msk);
    // 10. fine block-sparse attention
    fattn_kernel<<<dim3(NTOK, NKV), 256>>>(qkv, sel, msk, fout);
    // 11. gates
    gate_kernel<<<NTOK, 256>>>(x, gate_w, gate_b, gate);
    // 12. gated merge
    combine_kernel<<<(NTOK * DIM + 255) / 256, 256>>>(gate, cout, fout, comb);
    // 13. output projection (HMMA): 1024 x 1024 x 1024
    hgemm_kernel<<<dim3(DIM / 64, NTOK / 128), 256, HS_BYTES>>>(
        comb, DIM, w_out, DIM, out, DIM, DIM);
}

// round 10
// speedup vs baseline: 6.1539x; 1.2127x over previous
#include <cuda_runtime.h>
#include <cuda_bf16.h>
#include <math.h>
#include <stdint.h>

#define NHEADS 16
#define NKV 4
#define DH 64
#define NTOK 1024
#define DIM 1024
#define BS 32
#define NW 32
#define JW 33          // MEM + NW
#define NSEL 8
#define NBLK 9         // NSEL + own
#define JTOT 288       // NBLK*BS
#define CDIM 2048
#define HID 2048
#define QKVD 1536
#define PE_SZ (NKV * NW * CDIM)      // 262144
#define HID_SZ (NKV * NW * HID)      // 262144

// ---------------- scratch (static device globals; no runtime alloc) --------
__device__ float g_x[NTOK * DIM];
__device__ float g_qkv[NTOK * QKVD];
__device__ float g_pe[2 * PE_SZ];
__device__ float g_part[8 * HID_SZ];
__device__ float g_hid[2 * HID_SZ];
__device__ float g_craw[2 * NKV * NW * DH];
__device__ float g_ck[NKV * JW * DH];
__device__ float g_cv[NKV * JW * DH];
__device__ float g_csim[NHEADS * NTOK * JW];
__device__ float g_cout[NHEADS * NTOK * DH];
__device__ float g_fout[NHEADS * NTOK * DH];
__device__ int   g_sel[NKV * NTOK * NBLK];
__device__ int   g_msk[NKV * NTOK * NBLK];
__device__ float g_gate[NTOK * 32];
__device__ float g_comb[NTOK * DIM];

// ============ HMMA (mma.sync m16n8k16 bf16) split-precision GEMM ============
// CTA: 256 threads = 8 warps in 4(m) x 2(n); CTA tile 128 x 64, k-chunk 32.
// A smem stride 40 bf16 (20 u32); B smem stride 72 bf16 (36 u32) so that the
// transposed uint4 stores AND the fragment loads are bank-conflict-free.
#define HS_ABUF 2560           // 128*20 u32
#define HS_BBUF 2304           // 64*36 u32
#define HS_BUF  (2 * HS_ABUF + 2 * HS_BBUF)   // 9728 u32
#define HS_BYTES (2 * HS_BUF * 4)             // 77824 bytes

__device__ __forceinline__ void mma16816(float* c, const uint32_t* a, const uint32_t* b) {
    asm volatile(
        "mma.sync.aligned.m16n8k16.row.col.f32.bf16.bf16.f32 "
        "{%0,%1,%2,%3}, {%4,%5,%6,%7}, {%8,%9}, {%0,%1,%2,%3};\n"
        : "+f"(c[0]), "+f"(c[1]), "+f"(c[2]), "+f"(c[3])
        : "r"(a[0]), "r"(a[1]), "r"(a[2]), "r"(a[3]), "r"(b[0]), "r"(b[1]));
}
__device__ __forceinline__ uint32_t pack_hi(float x, float y) {
    __nv_bfloat162 t(__float2bfloat16(x), __float2bfloat16(y));
    return *(uint32_t*)&t;
}
__device__ __forceinline__ uint32_t pack_lo(float x, float y) {
    __nv_bfloat16 hx = __float2bfloat16(x), hy = __float2bfloat16(y);
    __nv_bfloat162 t(__float2bfloat16(x - __bfloat162float(hx)),
                     __float2bfloat16(y - __bfloat162float(hy)));
    return *(uint32_t*)&t;
}

__device__ __forceinline__ void store_chunkA(uint32_t* Ahi, uint32_t* Alo,
                                             const float4* aR, int tid) {
#pragma unroll
    for (int v = 0; v < 4; v++) {
        int idx = v * 256 + tid; int row = idx >> 3, q = idx & 7;
        uint2 h = make_uint2(pack_hi(aR[v].x, aR[v].y), pack_hi(aR[v].z, aR[v].w));
        uint2 l = make_uint2(pack_lo(aR[v].x, aR[v].y), pack_lo(aR[v].z, aR[v].w));
        *(uint2*)&Ahi[row * 20 + q * 2] = h;
        *(uint2*)&Alo[row * 20 + q * 2] = l;
    }
}
__device__ __forceinline__ void store_chunkB(uint32_t* Bhi, uint32_t* Blo,
                                             const float* bReg, int tid) {
    int n = tid & 63, kh = tid >> 6;
    uint4 h4, l4;
    h4.x = pack_hi(bReg[0], bReg[1]); h4.y = pack_hi(bReg[2], bReg[3]);
    h4.z = pack_hi(bReg[4], bReg[5]); h4.w = pack_hi(bReg[6], bReg[7]);
    l4.x = pack_lo(bReg[0], bReg[1]); l4.y = pack_lo(bReg[2], bReg[3]);
    l4.z = pack_lo(bReg[4], bReg[5]); l4.w = pack_lo(bReg[6], bReg[7]);
    *(uint4*)&((__nv_bfloat16*)Bhi)[n * 72 + kh * 8] = h4;
    *(uint4*)&((__nv_bfloat16*)Blo)[n * 72 + kh * 8] = l4;
}

// C[bm:bm+128, bn:bn+64] = A(.,lda) @ B(.,ldb), fp32 out. K % 32 == 0.
__device__ __forceinline__ void hgemm_body(
    const float* __restrict__ A, int lda,
    const float* __restrict__ B, int ldb,
    float* __restrict__ C, int ldc,
    int K, int bm, int bn)
{
    extern __shared__ uint32_t smu[];
    int tid = threadIdx.x, wid = tid >> 5, lane = tid & 31;
    int mwarp = (wid & 3) * 32;
    int nwarp = (wid >> 2) * 32;
    int r = lane >> 2, cq = lane & 3;
    int bn_n = tid & 63, bn_kh = tid >> 6;

    float4 aR[4];
    float bReg[8];
    float acc[2][4][4] = {};

    // prologue: load chunk 0
#pragma unroll
    for (int v = 0; v < 4; v++) {
        int idx = v * 256 + tid;
        aR[v] = *(const float4*)&A[(bm + (idx >> 3)) * lda + (idx & 7) * 4];
    }
#pragma unroll
    for (int u = 0; u < 8; u++)
        bReg[u] = B[(bn_kh * 8 + u) * ldb + bn + bn_n];

    int nk = K >> 5;
    int buf = 0;
    store_chunkA(smu, smu + HS_ABUF, aR, tid);
    store_chunkB(smu + 2 * HS_ABUF, smu + 2 * HS_ABUF + HS_BBUF, bReg, tid);
    __syncthreads();

    for (int kt = 0; kt < nk; kt++) {
        if (kt + 1 < nk) {
            int k0 = (kt + 1) << 5;
#pragma unroll
            for (int v = 0; v < 4; v++) {
                int idx = v * 256 + tid;
                aR[v] = *(const float4*)&A[(bm + (idx >> 3)) * lda + k0 + (idx & 7) * 4];
            }
#pragma unroll
            for (int u = 0; u < 8; u++)
                bReg[u] = B[(k0 + bn_kh * 8 + u) * ldb + bn + bn_n];
        }
        uint32_t* Ahi = smu + buf * HS_BUF; uint32_t* Alo = Ahi + HS_ABUF;
        uint32_t* Bhi = Alo + HS_ABUF;      uint32_t* Blo = Bhi + HS_BBUF;
#pragma unroll
        for (int k16 = 0; k16 < 2; k16++) {
            int kp = k16 * 8;
            uint32_t ah[2][4], al[2][4], bh[4][2], bl[4][2];
#pragma unroll
            for (int ma = 0; ma < 2; ma++) {
                int r0 = (mwarp + ma * 16 + r) * 20;
                ah[ma][0] = Ahi[r0 + kp + cq];        al[ma][0] = Alo[r0 + kp + cq];
                ah[ma][1] = Ahi[r0 + 160 + kp + cq];  al[ma][1] = Alo[r0 + 160 + kp + cq];
                ah[ma][2] = Ahi[r0 + kp + 4 + cq];    al[ma][2] = Alo[r0 + kp + 4 + cq];
                ah[ma][3] = Ahi[r0 + 160 + kp + 4 + cq]; al[ma][3] = Alo[r0 + 160 + kp + 4 + cq];
            }
#pragma unroll
            for (int na = 0; na < 4; na++) {
                int n0 = (nwarp + na * 8 + r) * 36;
                bh[na][0] = Bhi[n0 + kp + cq];     bl[na][0] = Blo[n0 + kp + cq];
                bh[na][1] = Bhi[n0 + kp + 4 + cq]; bl[na][1] = Blo[n0 + kp + 4 + cq];
            }
#pragma unroll
            for (int ma = 0; ma < 2; ma++)
#pragma unroll
                for (int na = 0; na < 4; na++) {
                    mma16816(acc[ma][na], ah[ma], bh[na]);
                    mma16816(acc[ma][na], ah[ma], bl[na]);
                    mma16816(acc[ma][na], al[ma], bh[na]);
                }
        }
        if (kt + 1 < nk) {
            uint32_t* nAhi = smu + (buf ^ 1) * HS_BUF;
            store_chunkA(nAhi, nAhi + HS_ABUF, aR, tid);
            store_chunkB(nAhi + 2 * HS_ABUF, nAhi + 2 * HS_ABUF + HS_BBUF, bReg, tid);
            __syncthreads();
            buf ^= 1;
        }
    }
#pragma unroll
    for (int ma = 0; ma < 2; ma++)
#pragma unroll
        for (int na = 0; na < 4; na++) {
            int row = bm + mwarp + ma * 16 + r;
            int col = bn + nwarp + na * 8 + cq * 2;
            *(float2*)&C[row * ldc + col] =
                make_float2(acc[ma][na][0], acc[ma][na][1]);
            *(float2*)&C[(row + 8) * ldc + col] =
                make_float2(acc[ma][na][2], acc[ma][na][3]);
        }
}

__global__ void hgemm_kernel(const float* __restrict__ A, int lda,
                             const float* __restrict__ B, int ldb,
                             float* __restrict__ C, int ldc, int K) {
    hgemm_body(A, lda, B, ldb, C, ldc, K, blockIdx.y * 128, blockIdx.x * 64);
}

__global__ void mlp1_h_kernel(const float* __restrict__ pe,
                              const float* __restrict__ k_w1,
                              const float* __restrict__ v_w1,
                              float* __restrict__ part) {
    int z = blockIdx.z;                  // kv*4 + ks
    int kv = z >> 2, ks = z & 3;
    hgemm_body(pe + kv * PE_SZ + ks * 512, CDIM,
               (kv ? v_w1 : k_w1) + ks * 512 * HID, HID,
               part + z * HID_SZ, HID, 512, 0, blockIdx.x * 64);
}

// ---------------- RMSNorm ---------------------------------------------------
__global__ void rmsnorm_kernel(const float* __restrict__ inp,
                               const float* __restrict__ gw,
                               float* __restrict__ x) {
    int i = blockIdx.x, t = threadIdx.x;
    __shared__ float red[256];
    float s = 0.f;
    for (int d = t; d < DIM; d += 256) { float v = inp[i * DIM + d]; s += v * v; }
    red[t] = s; __syncthreads();
    for (int o = 128; o; o >>= 1) { if (t < o) red[t] += red[t + o]; __syncthreads(); }
    float r = 1.f / sqrtf(red[0] / (float)DIM + 1e-6f);
    for (int d = t; d < DIM; d += 256)
        x[i * DIM + d] = inp[i * DIM + d] * r * gw[d];
}

// reduce split-K partials + bias + relu -> hid
__global__ void mlp1_reduce_kernel(const float* __restrict__ part,
                                   const float* __restrict__ k_b1,
                                   const float* __restrict__ v_b1,
                                   float* __restrict__ hid) {
    int idx = blockIdx.x * 256 + threadIdx.x;   // 2*HID_SZ
    if (idx >= 2 * HID_SZ) return;
    int kv = idx >> 18;
    int rem = idx & (HID_SZ - 1);
    int n = rem & (HID - 1);
    float s = part[(kv * 4 + 0) * HID_SZ + rem] + part[(kv * 4 + 1) * HID_SZ + rem]
            + part[(kv * 4 + 2) * HID_SZ + rem] + part[(kv * 4 + 3) * HID_SZ + rem]
            + (kv ? v_b1[n] : k_b1[n]);
    hid[idx] = fmaxf(s, 0.f);
}

// fused K+V MLP layer 2: 4 rows per CTA (w2 re-use)
__global__ void mlp2_kernel(const float* __restrict__ hid,
                            const float* __restrict__ k_w2,
                            const float* __restrict__ v_w2,
                            const float* __restrict__ k_b2,
                            const float* __restrict__ v_b2,
                            float* __restrict__ craw) {
    int r0 = blockIdx.x * 4, kv = blockIdx.y;
    int tid = threadIdx.x;               // 256
    int col = tid & 63, ks = tid >> 6;
    const float* h0 = hid + kv * HID_SZ + r0 * HID + ks * 512;
    const float* wb = (kv ? v_w2 : k_w2) + ks * 512 * DH + col;
    float acc[4] = {};
#pragma unroll 4
    for (int k = 0; k < 512; k++) {
        float w = wb[k * DH];
        acc[0] += h0[k] * w;
        acc[1] += h0[HID + k] * w;
        acc[2] += h0[2 * HID + k] * w;
        acc[3] += h0[3 * HID + k] * w;
    }
    __shared__ float red[4][256];
#pragma unroll
    for (int j = 0; j < 4; j++) red[j][tid] = acc[j];
    __syncthreads();
    if (ks == 0) {
        float b = (kv ? v_b2[col] : k_b2[col]);
#pragma unroll
        for (int j = 0; j < 4; j++)
            craw[kv * (NKV * NW * DH) + (r0 + j) * DH + col] =
                red[j][col] + red[j][col + 64] + red[j][col + 128]
                + red[j][col + 192] + b;
    }
}

// ---------------- gates -----------------------------------------------------
__global__ void gate_kernel(const float* __restrict__ x,
                            const float* __restrict__ gw,
                            const float* __restrict__ gb,
                            float* __restrict__ gate) {
    int i = blockIdx.x;
    int tid = threadIdx.x;               // 256
    int col = tid & 31, ks = tid >> 5;
    const float* xr = x + i * DIM + ks * 128;
    const float* wb = gw + ks * 128 * 32 + col;
    float acc = 0.f;
#pragma unroll 8
    for (int k = 0; k < 128; k++) acc += xr[k] * wb[k * 32];
    __shared__ float red[256];
    red[tid] = acc; __syncthreads();
    if (tid < 32) {
        float v = gb[col];
#pragma unroll
        for (int s = 0; s < 8; s++) v += red[col + s * 32];
        gate[i * 32 + col] = v;
    }
}

// ---------------- fused build of both compress-MLP inputs -------------------
__global__ void build_pe_kernel(const float* __restrict__ qkv,
                                const float* __restrict__ k_pos,
                                const float* __restrict__ v_pos,
                                float* __restrict__ pe) {
    int idx = blockIdx.x * 256 + threadIdx.x;   // 2*PE_SZ
    if (idx >= 2 * PE_SZ) return;
    int kv = idx >> 18;
    int rem = idx & (PE_SZ - 1);
    int d = rem & 63;
    int t = (rem >> 6) & 31;
    int w = (rem >> 11) & 31;
    int h = rem >> 16;
    const float* pos = kv ? v_pos : k_pos;
    pe[idx] = qkv[(w * BS + t) * QKVD + ((kv ? 20 : 16) + h) * DH + d]
            + pos[(h * BS + t) * DH + d];
}

// ---------------- fused prepend of mem tokens to ck and cv ------------------
__global__ void assemble_c_kernel(const float* __restrict__ craw,
                                  const float* __restrict__ mem_kv,
                                  float* __restrict__ ck,
                                  float* __restrict__ cv) {
    int idx = blockIdx.x * 256 + threadIdx.x;
    if (idx >= 2 * NKV * JW * DH) return;
    int kv = idx / (NKV * JW * DH);
    int rem = idx % (NKV * JW * DH);
    int d = rem & 63;
    int j = (rem >> 6) % JW;
    int h = rem / (JW * DH);
    float* dst = kv ? cv : ck;
    dst[rem] = (j == 0) ? mem_kv[kv * (NKV * DH) + h * DH + d]
                        : craw[kv * (NKV * NW * DH) + (h * NW + (j - 1)) * DH + d];
}

// ---------------- compressed attention, tiled (pre-rotary q) ----------------
// CTA = (32-token tile, head). ck/cv staged once per CTA.
__global__ void cattn_kernel(const float* __restrict__ qkv,
                             const float* __restrict__ ck,
                             const float* __restrict__ cv,
                             float* __restrict__ csim_out,
                             float* __restrict__ cout) {
    int i0 = blockIdx.x * 32, head = blockIdx.y, kvh = head >> 2;
    int tid = threadIdx.x;               // 256
    __shared__ float cks[JW][DH + 1];
    __shared__ float cvs[JW][DH + 1];
    __shared__ float qs[32][DH + 1];
    __shared__ float sims[32][JW];
    for (int v = tid; v < JW * DH; v += 256) {
        int j = v >> 6, d = v & 63;
        cks[j][d] = ck[kvh * JW * DH + v];
        cvs[j][d] = cv[kvh * JW * DH + v];
    }
    for (int v = tid; v < 32 * DH; v += 256) {
        int q = v >> 6, d = v & 63;
        qs[q][d] = qkv[(i0 + q) * QKVD + head * DH + d];
    }
    __syncthreads();
    int q = tid >> 3;
    for (int j = tid & 7; j < JW; j += 8) {
        float s = 0.f;
#pragma unroll
        for (int d = 0; d < DH; d++) s += qs[q][d] * cks[j][d];
        s *= 0.125f;
        sims[q][j] = s;
        csim_out[(head * NTOK + i0 + q) * JW + j] = s;
    }
    __syncthreads();
    if (tid < 32) {
        float m = -1e30f;
        for (int j = 0; j < JW; j++) m = fmaxf(m, sims[tid][j]);
        float den = 0.f;
        for (int j = 0; j < JW; j++) { float e = expf(sims[tid][j] - m); sims[tid][j] = e; den += e; }
        float inv = 1.f / den;
        for (int j = 0; j < JW; j++) sims[tid][j] *= inv;
    }
    __syncthreads();
    int d0 = (tid & 7) * 8;
    float acc[8] = {};
    for (int j = 0; j < JW; j++) {
        float p = sims[q][j];
#pragma unroll
        for (int u = 0; u < 8; u++) acc[u] += p * cvs[j][d0 + u];
    }
#pragma unroll
    for (int u = 0; u < 8; u++)
        cout[(head * NTOK + i0 + q) * DH + d0 + u] = acc[u];
}

// ---------------- interleaved rotary on q + k (in-place in qkv) -------------
__global__ void rotary_kernel(float* __restrict__ qkv) {
    int i = blockIdx.x;
    int tid = threadIdx.x;               // 640
    int hh = tid >> 5, p = tid & 31;
    float inv = exp2f(-(float)(2 * p) * (0.015625f * 13.287712379549449f));
    float ang = (float)i * inv;
    float c = cosf(ang), s = sinf(ang);
    float* base = qkv + i * QKVD + hh * DH;
    float x0 = base[2 * p], x1 = base[2 * p + 1];
    base[2 * p]     = x0 * c - x1 * s;
    base[2 * p + 1] = x1 * c + x0 * s;
}

// ---------------- block selection (top-8 + own block) -----------------------
__global__ void select_kernel(const float* __restrict__ csim,
                              int* __restrict__ sel, int* __restrict__ msk) {
    int idx = blockIdx.x * blockDim.x + threadIdx.x;   // NKV*NTOK = 4096
    if (idx >= NKV * NTOK) return;
    int h = idx >> 10, i = idx & 1023;
    float imp[NW];
    for (int w = 0; w < NW; w++) {
        float s = 0.f;
        for (int g = 0; g < 4; g++)
            s += csim[((h * 4 + g) * NTOK + i) * JW + 1 + w];
        imp[w] = s * 0.25f;
    }
    float m = -1000.f;
    for (int w = 0; w < NW; w++) m = fmaxf(m, imp[w]);
    float den = expf(-1000.f - m);
    float p[NW];
    for (int w = 0; w < NW; w++) { p[w] = expf(imp[w] - m); den += p[w]; }
    float inv = 1.f / den;
    bool taken[NW];
    for (int w = 0; w < NW; w++) taken[w] = false;
    for (int s = 0; s < NSEL; s++) {
        int best = 0; float bv = -1.f;
        for (int w = 0; w < NW; w++)
            if (!taken[w] && p[w] > bv) { bv = p[w]; best = w; }
        taken[best] = true;
        sel[idx * NBLK + s] = best;
        msk[idx * NBLK + s] = (bv * inv > 1e-10f) ? 1 : 0;
    }
    sel[idx * NBLK + NSEL] = i >> 5;
    msk[idx * NBLK + NSEL] = 1;
}

// ---------------- fine (block-sparse) attention -----------------------------
__global__ void fattn_kernel(const float* __restrict__ qkv,
                             const int* __restrict__ sel,
                             const int* __restrict__ msk,
                             float* __restrict__ fout) {
    int i = blockIdx.x, kvh = blockIdx.y;
    int tid = threadIdx.x;               // 256
    __shared__ float qs[4][DH];
    __shared__ float kblk[BS][DH + 1];
    __shared__ float sims[4][JTOT];
    __shared__ int ssel[NBLK];
    __shared__ int smask[NBLK];
    __shared__ float gmax[4], ginv[4];
    if (tid < NBLK) {
        ssel[tid]  = sel[(kvh * NTOK + i) * NBLK + tid];
        smask[tid] = msk[(kvh * NTOK + i) * NBLK + tid];
    }
    { int g = tid >> 6, d = tid & 63;
      qs[g][d] = qkv[i * QKVD + (kvh * 4 + g) * DH + d]; }
    __syncthreads();
    for (int b = 0; b < NBLK; b++) {
        int blk = ssel[b];
        for (int l = tid; l < BS * DH / 4; l += 256) {
            int t = l >> 4, dq = (l & 15) * 4;
            float4 v = *(const float4*)&qkv[(blk * BS + t) * QKVD + (16 + kvh) * DH + dq];
            kblk[t][dq] = v.x; kblk[t][dq + 1] = v.y;
            kblk[t][dq + 2] = v.z; kblk[t][dq + 3] = v.w;
        }
        __syncthreads();
        if (tid < 128) {
            int g = tid >> 5, t = tid & 31;
            float s = 0.f;
#pragma unroll
            for (int d = 0; d < DH; d++) s += qs[g][d] * kblk[t][d];
            sims[g][b * BS + t] = smask[b] ? s * 0.125f : -1e30f;
        }
        __syncthreads();
    }
    int w = tid >> 5, lane = tid & 31;
    if (w < 4) {
        float m = -1e30f;
        for (int j = lane; j < JTOT; j += 32) m = fmaxf(m, sims[w][j]);
        for (int o = 16; o; o >>= 1) m = fmaxf(m, __shfl_xor_sync(0xffffffffu, m, o));
        float s = 0.f;
        for (int j = lane; j < JTOT; j += 32) s += expf(sims[w][j] - m);
        for (int o = 16; o; o >>= 1) s += __shfl_xor_sync(0xffffffffu, s, o);
        if (lane == 0) { gmax[w] = m; ginv[w] = 1.f / s; }
    }
    __syncthreads();
    for (int l = tid; l < 4 * JTOT; l += 256) {
        int g = l / JTOT, j = l % JTOT;
        sims[g][j] = expf(sims[g][j] - gmax[g]) * ginv[g];
    }
    __syncthreads();
    // V pass: stage each selected V block in smem (reuse kblk)
    int g = tid >> 6, d = tid & 63;
    float acc = 0.f;
    for (int b = 0; b < NBLK; b++) {
        int blk = ssel[b];
        for (int l = tid; l < BS * DH / 4; l += 256) {
            int t = l >> 4, dq = (l & 15) * 4;
            float4 v = *(const float4*)&qkv[(blk * BS + t) * QKVD + (20 + kvh) * DH + dq];
            kblk[t][dq] = v.x; kblk[t][dq + 1] = v.y;
            kblk[t][dq + 2] = v.z; kblk[t][dq + 3] = v.w;
        }
        __syncthreads();
#pragma unroll
        for (int t = 0; t < BS; t++)
            acc += sims[g][b * BS + t] * kblk[t][d];
        __syncthreads();
    }
    fout[((kvh * 4 + g) * NTOK + i) * DH + d] = acc;
}

// ---------------- sigmoid-gated merge of the two branches -------------------
__global__ void combine_kernel(const float* __restrict__ gate_logits,
                               const float* __restrict__ cout,
                               const float* __restrict__ fout,
                               float* __restrict__ comb) {
    int idx = blockIdx.x * 256 + threadIdx.x;
    if (idx >= NTOK * DIM) return;
    int d = idx & 63, head = (idx >> 6) & 15, i = idx >> 10;
    float l0 = gate_logits[i * 32 + head * 2];
    float l1 = gate_logits[i * 32 + head * 2 + 1];
    float s0 = 1.f / (1.f + expf(-l0));
    float s1 = 1.f / (1.f + expf(-l1));
    comb[idx] = s0 * cout[(head * NTOK + i) * DH + d]
              + s1 * fout[(head * NTOK + i) * DH + d];
}

// ---------------- host launch -----------------------------------------------
extern "C" void kernel_launch(void* const* d_in, const int* in_sizes, int n_in,
                              void* d_out, int out_size) {
    const float* inp    = (const float*)d_in[0];
    const float* g_norm = (const float*)d_in[1];
    const float* w_qkv  = (const float*)d_in[2];
    const float* mem_kv = (const float*)d_in[3];
    const float* k_pos  = (const float*)d_in[4];
    const float* v_pos  = (const float*)d_in[5];
    const float* k_w1   = (const float*)d_in[6];
    const float* k_b1   = (const float*)d_in[7];
    const float* k_w2   = (const float*)d_in[8];
    const float* k_b2   = (const float*)d_in[9];
    const float* v_w1   = (const float*)d_in[10];
    const float* v_b1   = (const float*)d_in[11];
    const float* v_w2   = (const float*)d_in[12];
    const float* v_b2   = (const float*)d_in[13];
    const float* gate_w = (const float*)d_in[14];
    const float* gate_b = (const float*)d_in[15];
    const float* w_out  = (const float*)d_in[16];
    float* out = (float*)d_out;

    float *x, *qkv, *pe, *part, *hid, *craw, *ck, *cv, *csim, *cout, *fout, *gate, *comb;
    int *sel, *msk;
    cudaGetSymbolAddress((void**)&x,    g_x);
    cudaGetSymbolAddress((void**)&qkv,  g_qkv);
    cudaGetSymbolAddress((void**)&pe,   g_pe);
    cudaGetSymbolAddress((void**)&part, g_part);
    cudaGetSymbolAddress((void**)&hid,  g_hid);
    cudaGetSymbolAddress((void**)&craw, g_craw);
    cudaGetSymbolAddress((void**)&ck,   g_ck);
    cudaGetSymbolAddress((void**)&cv,   g_cv);
    cudaGetSymbolAddress((void**)&csim, g_csim);
    cudaGetSymbolAddress((void**)&cout, g_cout);
    cudaGetSymbolAddress((void**)&fout, g_fout);
    cudaGetSymbolAddress((void**)&gate, g_gate);
    cudaGetSymbolAddress((void**)&comb, g_comb);
    cudaGetSymbolAddress((void**)&sel,  g_sel);
    cudaGetSymbolAddress((void**)&msk,  g_msk);

    cudaFuncSetAttribute(hgemm_kernel,
        cudaFuncAttributeMaxDynamicSharedMemorySize, HS_BYTES);
    cudaFuncSetAttribute(mlp1_h_kernel,
        cudaFuncAttributeMaxDynamicSharedMemorySize, HS_BYTES);

    // 1. RMSNorm
    rmsnorm_kernel<<<NTOK, 256>>>(inp, g_norm, x);
    // 2. QKV projection (HMMA): 1024 x 1536 x 1024
    hgemm_kernel<<<dim3(QKVD / 64, NTOK / 128), 256, HS_BYTES>>>(
        x, DIM, w_qkv, QKVD, qkv, QKVD, DIM);
    // 3. fused K+V compress-MLP input
    build_pe_kernel<<<(2 * PE_SZ + 255) / 256, 256>>>(qkv, k_pos, v_pos, pe);
    // 4. fused K+V MLP layer 1 (HMMA, split-K=4) + reduce
    mlp1_h_kernel<<<dim3(HID / 64, 1, 8), 256, HS_BYTES>>>(pe, k_w1, v_w1, part);
    mlp1_reduce_kernel<<<(2 * HID_SZ + 255) / 256, 256>>>(part, k_b1, v_b1, hid);
    // 5. fused K+V MLP layer 2 (4 rows per CTA)
    mlp2_kernel<<<dim3(NKV * NW / 4, 2), 256>>>(hid, k_w2, v_w2, k_b2, v_b2, craw);
    // 6. assemble ck / cv with mem token
    assemble_c_kernel<<<(2 * NKV * JW * DH + 255) / 256, 256>>>(craw, mem_kv, ck, cv);
    // 7. compressed attention, tiled (pre-rotary q)
    cattn_kernel<<<dim3(NTOK / 32, NHEADS), 256>>>(qkv, ck, cv, csim, cout);
    // 8. rotary on q + k (in place)
    rotary_kernel<<<NTOK, 640>>>(qkv);
    // 9. block selection
    select_kernel<<<16, 256>>>(csim, sel, msk);
    // 10. fine block-sparse attention
    fattn_kernel<<<dim3(NTOK, NKV), 256>>>(qkv, sel, msk, fout);
    // 11. gates
    gate_kernel<<<NTOK, 256>>>(x, gate_w, gate_b, gate);
    // 12. gated merge
    combine_kernel<<<(NTOK * DIM + 255) / 256, 256>>>(gate, cout, fout, comb);
    // 13. output projection (HMMA): 1024 x 1024 x 1024
    hgemm_kernel<<<dim3(DIM / 64, NTOK / 128), 256, HS_BYTES>>>(
        comb, DIM, w_out, DIM, out, DIM, DIM);
}